// round 2
// baseline (speedup 1.0000x reference)
#include <cuda_runtime.h>
#include <math.h>

#define EMBED 1024
#define HEADS 16
#define HEAD_DIM 64
#define HIDDEN 4096
#define BATCH 2
#define SEQ 2048
#define ROWS (BATCH * SEQ)
#define QKV_C (3 * EMBED)

#define ATTN_SMEM (4 * 64 * 65 * 4)

// Scratch (no cudaMalloc allowed)
__device__ float g_xn[(size_t)ROWS * EMBED];
__device__ float g_qkv[(size_t)ROWS * QKV_C];
__device__ float g_att[(size_t)ROWS * EMBED];
__device__ float g_x1[(size_t)ROWS * EMBED];
__device__ float g_h[(size_t)ROWS * HIDDEN];

// ---------------------------------------------------------------------------
// LayerNorm: one block per row of 1024, 256 threads, float4 per thread
// ---------------------------------------------------------------------------
__global__ __launch_bounds__(256) void ln_kernel(const float* __restrict__ x,
                                                 const float* __restrict__ w,
                                                 const float* __restrict__ b,
                                                 float* __restrict__ out) {
    int row = blockIdx.x;
    int t = threadIdx.x;
    const float4* xr = (const float4*)(x + (size_t)row * EMBED);
    float4 v = xr[t];
    float s = v.x + v.y + v.z + v.w;
    float q = v.x * v.x + v.y * v.y + v.z * v.z + v.w * v.w;
#pragma unroll
    for (int o = 16; o > 0; o >>= 1) {
        s += __shfl_xor_sync(0xffffffffu, s, o);
        q += __shfl_xor_sync(0xffffffffu, q, o);
    }
    __shared__ float rs[8], rq[8];
    if ((t & 31) == 0) { rs[t >> 5] = s; rq[t >> 5] = q; }
    __syncthreads();
    float ts = 0.f, tq = 0.f;
#pragma unroll
    for (int i = 0; i < 8; i++) { ts += rs[i]; tq += rq[i]; }
    float mu = ts * (1.0f / EMBED);
    float var = tq * (1.0f / EMBED) - mu * mu;
    float rstd = rsqrtf(var + 1e-5f);
    float4 wv = ((const float4*)w)[t];
    float4 bv = ((const float4*)b)[t];
    float4 o;
    o.x = (v.x - mu) * rstd * wv.x + bv.x;
    o.y = (v.y - mu) * rstd * wv.y + bv.y;
    o.z = (v.z - mu) * rstd * wv.z + bv.z;
    o.w = (v.w - mu) * rstd * wv.w + bv.w;
    ((float4*)(out + (size_t)row * EMBED))[t] = o;
}

// ---------------------------------------------------------------------------
// GEMM: C[M,Nc] = A[M,K] @ W[K,Nc] + bias, with epilogue variants.
// 128x128 block tile, BK=8, 256 threads, 8x8 register micro-tile.
// EPI: 0 = bias only, 1 = bias + exact GELU, 2 = bias + residual add
// ---------------------------------------------------------------------------
__device__ __forceinline__ float gelu_exact(float x) {
    return 0.5f * x * (1.0f + erff(x * 0.70710678118654752f));
}

template <int EPI>
__global__ __launch_bounds__(256) void gemm_kernel(const float* __restrict__ A,
                                                   const float* __restrict__ W,
                                                   const float* __restrict__ bias,
                                                   const float* __restrict__ res,
                                                   float* __restrict__ C,
                                                   int K, int Nc) {
    __shared__ float As[8][128];
    __shared__ float Ws[8][128];
    const int tid = threadIdx.x;
    const int tm = tid >> 4, tn = tid & 15;
    const int brow = blockIdx.y, bcol = blockIdx.x;

    const int arow = tid >> 1;
    const int ak = (tid & 1) * 4;
    const float* Ap = A + (size_t)(brow * 128 + arow) * K + ak;
    const int wr = tid >> 5;
    const int wc = (tid & 31) * 4;
    const float* Wp = W + (size_t)wr * Nc + bcol * 128 + wc;

    float acc[8][8];
#pragma unroll
    for (int i = 0; i < 8; i++)
#pragma unroll
        for (int j = 0; j < 8; j++) acc[i][j] = 0.f;

    for (int kt = 0; kt < K; kt += 8) {
        float4 av = *(const float4*)(Ap + kt);
        float4 wv = *(const float4*)(Wp + (size_t)kt * Nc);
        As[ak + 0][arow] = av.x;
        As[ak + 1][arow] = av.y;
        As[ak + 2][arow] = av.z;
        As[ak + 3][arow] = av.w;
        *(float4*)&Ws[wr][wc] = wv;
        __syncthreads();
#pragma unroll
        for (int kk = 0; kk < 8; kk++) {
            float a[8], b[8];
            *(float4*)(a)     = *(const float4*)&As[kk][tm * 8];
            *(float4*)(a + 4) = *(const float4*)&As[kk][tm * 8 + 4];
            *(float4*)(b)     = *(const float4*)&Ws[kk][tn * 8];
            *(float4*)(b + 4) = *(const float4*)&Ws[kk][tn * 8 + 4];
#pragma unroll
            for (int i = 0; i < 8; i++)
#pragma unroll
                for (int j = 0; j < 8; j++)
                    acc[i][j] = fmaf(a[i], b[j], acc[i][j]);
        }
        __syncthreads();
    }

    const int col0 = bcol * 128 + tn * 8;
    float bv[8];
    *(float4*)(bv)     = *(const float4*)(bias + col0);
    *(float4*)(bv + 4) = *(const float4*)(bias + col0 + 4);
#pragma unroll
    for (int i = 0; i < 8; i++) {
        size_t r = (size_t)(brow * 128 + tm * 8 + i);
        float* cp = C + r * Nc + col0;
        float o[8];
#pragma unroll
        for (int j = 0; j < 8; j++) o[j] = acc[i][j] + bv[j];
        if (EPI == 1) {
#pragma unroll
            for (int j = 0; j < 8; j++) o[j] = gelu_exact(o[j]);
        } else if (EPI == 2) {
            const float* rp = res + r * Nc + col0;
            float rv[8];
            *(float4*)(rv)     = *(const float4*)(rp);
            *(float4*)(rv + 4) = *(const float4*)(rp + 4);
#pragma unroll
            for (int j = 0; j < 8; j++) o[j] += rv[j];
        }
        *(float4*)(cp)     = *(float4*)(o);
        *(float4*)(cp + 4) = *(float4*)(o + 4);
    }
}

// ---------------------------------------------------------------------------
// Flash attention (fp32): grid (SEQ/64, BATCH*HEADS), 128 threads.
// Block handles 64 query rows of one (b,h). Tiles of 64 keys, online softmax.
// Thread (ty,tx): ty=tid>>3 owns rows ty*4..+3, tx=tid&7 owns cols tx*8..+7.
// ---------------------------------------------------------------------------
__global__ __launch_bounds__(128) void attn_kernel(const float* __restrict__ qkv,
                                                   float* __restrict__ out) {
    extern __shared__ float sm[];
    float* Qs = sm;                 // [64][65]
    float* Ks = Qs + 64 * 65;       // [64][65]
    float* Vs = Ks + 64 * 65;       // [64][65]
    float* Ps = Vs + 64 * 65;       // [64][65]

    const int bh = blockIdx.y;
    const int b = bh / HEADS, h = bh % HEADS;
    const int qblk = blockIdx.x;
    const int tid = threadIdx.x;
    const int ty = tid >> 3;   // 0..15
    const int tx = tid & 7;    // 0..7

    const float* qbase = qkv + (size_t)(b * SEQ + qblk * 64) * QKV_C + h * HEAD_DIM;
    const float* kbase = qkv + (size_t)(b * SEQ) * QKV_C + EMBED + h * HEAD_DIM;
    const float* vbase = qkv + (size_t)(b * SEQ) * QKV_C + 2 * EMBED + h * HEAD_DIM;

    // Load Q tile [64][64] (rows x head_dim)
    for (int it = tid; it < 64 * 16; it += 128) {
        int r = it >> 4, c4 = (it & 15) * 4;
        float4 v = *(const float4*)(qbase + (size_t)r * QKV_C + c4);
        float* d = Qs + r * 65 + c4;
        d[0] = v.x; d[1] = v.y; d[2] = v.z; d[3] = v.w;
    }

    float m_i[4], l_i[4], Oacc[4][8];
#pragma unroll
    for (int i = 0; i < 4; i++) {
        m_i[i] = -INFINITY;
        l_i[i] = 0.f;
#pragma unroll
        for (int j = 0; j < 8; j++) Oacc[i][j] = 0.f;
    }
    const float scale = 0.125f;  // 1/sqrt(64)

    for (int kt = 0; kt < SEQ; kt += 64) {
        __syncthreads();  // protect K/V/P from previous iteration's readers
        for (int it = tid; it < 64 * 16; it += 128) {
            int r = it >> 4, c4 = (it & 15) * 4;
            float4 kv = *(const float4*)(kbase + (size_t)(kt + r) * QKV_C + c4);
            float4 vv = *(const float4*)(vbase + (size_t)(kt + r) * QKV_C + c4);
            float* kd = Ks + r * 65 + c4;
            kd[0] = kv.x; kd[1] = kv.y; kd[2] = kv.z; kd[3] = kv.w;
            float* vd = Vs + r * 65 + c4;
            vd[0] = vv.x; vd[1] = vv.y; vd[2] = vv.z; vd[3] = vv.w;
        }
        __syncthreads();

        // S = Q @ K^T (micro-tile 4x8 per thread)
        float S[4][8];
#pragma unroll
        for (int i = 0; i < 4; i++)
#pragma unroll
            for (int j = 0; j < 8; j++) S[i][j] = 0.f;
        for (int k = 0; k < 64; k++) {
            float a[4], bb[8];
#pragma unroll
            for (int i = 0; i < 4; i++) a[i] = Qs[(ty * 4 + i) * 65 + k];
#pragma unroll
            for (int j = 0; j < 8; j++) bb[j] = Ks[(tx * 8 + j) * 65 + k];
#pragma unroll
            for (int i = 0; i < 4; i++)
#pragma unroll
                for (int j = 0; j < 8; j++)
                    S[i][j] = fmaf(a[i], bb[j], S[i][j]);
        }

        // Online softmax per row (row group = 8 lanes sharing ty)
        float alpha[4];
#pragma unroll
        for (int i = 0; i < 4; i++) {
            float mx = S[i][0] * scale;
#pragma unroll
            for (int j = 1; j < 8; j++) mx = fmaxf(mx, S[i][j] * scale);
#pragma unroll
            for (int o = 1; o < 8; o <<= 1)
                mx = fmaxf(mx, __shfl_xor_sync(0xffffffffu, mx, o));
            float mnew = fmaxf(m_i[i], mx);
            float sum = 0.f;
#pragma unroll
            for (int j = 0; j < 8; j++) {
                S[i][j] = __expf(S[i][j] * scale - mnew);
                sum += S[i][j];
            }
#pragma unroll
            for (int o = 1; o < 8; o <<= 1)
                sum += __shfl_xor_sync(0xffffffffu, sum, o);
            alpha[i] = __expf(m_i[i] - mnew);
            l_i[i] = l_i[i] * alpha[i] + sum;
            m_i[i] = mnew;
        }

        // Stage P to smem for the PV product
#pragma unroll
        for (int i = 0; i < 4; i++)
#pragma unroll
            for (int j = 0; j < 8; j++)
                Ps[(ty * 4 + i) * 65 + tx * 8 + j] = S[i][j];
        __syncthreads();

        // O = O*alpha + P @ V
#pragma unroll
        for (int i = 0; i < 4; i++)
#pragma unroll
            for (int j = 0; j < 8; j++) Oacc[i][j] *= alpha[i];
        for (int c = 0; c < 64; c++) {
            float p[4], vv[8];
#pragma unroll
            for (int i = 0; i < 4; i++) p[i] = Ps[(ty * 4 + i) * 65 + c];
#pragma unroll
            for (int j = 0; j < 8; j++) vv[j] = Vs[c * 65 + tx * 8 + j];
#pragma unroll
            for (int i = 0; i < 4; i++)
#pragma unroll
                for (int j = 0; j < 8; j++)
                    Oacc[i][j] = fmaf(p[i], vv[j], Oacc[i][j]);
        }
    }

    // Write normalized output: out[b, n, h*64 + d]
#pragma unroll
    for (int i = 0; i < 4; i++) {
        int n = qblk * 64 + ty * 4 + i;
        float inv = 1.0f / l_i[i];
        float* op = out + (size_t)(b * SEQ + n) * EMBED + h * HEAD_DIM + tx * 8;
        float o[8];
#pragma unroll
        for (int j = 0; j < 8; j++) o[j] = Oacc[i][j] * inv;
        *(float4*)(op)     = *(float4*)(o);
        *(float4*)(op + 4) = *(float4*)(o + 4);
    }
}

// ---------------------------------------------------------------------------
extern "C" void kernel_launch(void* const* d_in, const int* in_sizes, int n_in,
                              void* d_out, int out_size) {
    const float* x      = (const float*)d_in[0];
    const float* ln1_w  = (const float*)d_in[1];
    const float* ln1_b  = (const float*)d_in[2];
    const float* ln2_w  = (const float*)d_in[3];
    const float* ln2_b  = (const float*)d_in[4];
    const float* qkv_w  = (const float*)d_in[5];
    const float* qkv_b  = (const float*)d_in[6];
    const float* proj_w = (const float*)d_in[7];
    const float* proj_b = (const float*)d_in[8];
    const float* fc1_w  = (const float*)d_in[9];
    const float* fc1_b  = (const float*)d_in[10];
    const float* fc2_w  = (const float*)d_in[11];
    const float* fc2_b  = (const float*)d_in[12];
    float* out = (float*)d_out;

    void* p;
    cudaGetSymbolAddress(&p, g_xn);  float* xn  = (float*)p;
    cudaGetSymbolAddress(&p, g_qkv); float* qkv = (float*)p;
    cudaGetSymbolAddress(&p, g_att); float* att = (float*)p;
    cudaGetSymbolAddress(&p, g_x1);  float* x1  = (float*)p;
    cudaGetSymbolAddress(&p, g_h);   float* h   = (float*)p;

    cudaFuncSetAttribute(attn_kernel, cudaFuncAttributeMaxDynamicSharedMemorySize,
                         ATTN_SMEM);

    // x1 = x + proj(attn(ln1(x)))
    ln_kernel<<<ROWS, 256>>>(x, ln1_w, ln1_b, xn);
    gemm_kernel<0><<<dim3(QKV_C / 128, ROWS / 128), 256>>>(
        xn, qkv_w, qkv_b, nullptr, qkv, EMBED, QKV_C);
    attn_kernel<<<dim3(SEQ / 64, BATCH * HEADS), 128, ATTN_SMEM>>>(qkv, att);
    gemm_kernel<2><<<dim3(EMBED / 128, ROWS / 128), 256>>>(
        att, proj_w, proj_b, x, x1, EMBED, EMBED);

    // out = x1 + fc2(gelu(fc1(ln2(x1))))
    ln_kernel<<<ROWS, 256>>>(x1, ln2_w, ln2_b, xn);
    gemm_kernel<1><<<dim3(HIDDEN / 128, ROWS / 128), 256>>>(
        xn, fc1_w, fc1_b, nullptr, h, EMBED, HIDDEN);
    gemm_kernel<2><<<dim3(EMBED / 128, ROWS / 128), 256>>>(
        h, fc2_w, fc2_b, x1, out, HIDDEN, EMBED);
}

// round 3
// speedup vs baseline: 1.4769x; 1.4769x over previous
#include <cuda_runtime.h>
#include <math.h>
#include <stdint.h>

#define EMBED 1024
#define HEADS 16
#define HEAD_DIM 64
#define HIDDEN 4096
#define BATCH 2
#define SEQ 2048
#define ROWS (BATCH * SEQ)
#define QKV_C (3 * EMBED)

#define ATTN_SMEM (4 * 64 * 65 * 4)

// GEMM tiling
#define BM 128
#define BN 128
#define BK 32
#define APITCH 36    // floats; banks (4g+t) conflict-free for A fragments
#define BPITCH 136   // floats; banks (8t+g) conflict-free for B fragments
#define ASTG (BM * APITCH)
#define BSTG (BK * BPITCH)
#define GEMM_SMEM ((ASTG + BSTG) * 2 * 4)

// Scratch (no cudaMalloc allowed)
__device__ float g_xn[(size_t)ROWS * EMBED];
__device__ float g_qkv[(size_t)ROWS * QKV_C];
__device__ float g_att[(size_t)ROWS * EMBED];
__device__ float g_x1[(size_t)ROWS * EMBED];
__device__ float g_h[(size_t)ROWS * HIDDEN];

// ---------------------------------------------------------------------------
// LayerNorm
// ---------------------------------------------------------------------------
__global__ __launch_bounds__(256) void ln_kernel(const float* __restrict__ x,
                                                 const float* __restrict__ w,
                                                 const float* __restrict__ b,
                                                 float* __restrict__ out) {
    int row = blockIdx.x;
    int t = threadIdx.x;
    const float4* xr = (const float4*)(x + (size_t)row * EMBED);
    float4 v = xr[t];
    float s = v.x + v.y + v.z + v.w;
    float q = v.x * v.x + v.y * v.y + v.z * v.z + v.w * v.w;
#pragma unroll
    for (int o = 16; o > 0; o >>= 1) {
        s += __shfl_xor_sync(0xffffffffu, s, o);
        q += __shfl_xor_sync(0xffffffffu, q, o);
    }
    __shared__ float rs[8], rq[8];
    if ((t & 31) == 0) { rs[t >> 5] = s; rq[t >> 5] = q; }
    __syncthreads();
    float ts = 0.f, tq = 0.f;
#pragma unroll
    for (int i = 0; i < 8; i++) { ts += rs[i]; tq += rq[i]; }
    float mu = ts * (1.0f / EMBED);
    float var = tq * (1.0f / EMBED) - mu * mu;
    float rstd = rsqrtf(var + 1e-5f);
    float4 wv = ((const float4*)w)[t];
    float4 bv = ((const float4*)b)[t];
    float4 o;
    o.x = (v.x - mu) * rstd * wv.x + bv.x;
    o.y = (v.y - mu) * rstd * wv.y + bv.y;
    o.z = (v.z - mu) * rstd * wv.z + bv.z;
    o.w = (v.w - mu) * rstd * wv.w + bv.w;
    ((float4*)(out + (size_t)row * EMBED))[t] = o;
}

// ---------------------------------------------------------------------------
// tf32 tensor-core GEMM: C[M,Nc] = A[M,K] @ W[K,Nc] + bias (+epilogue)
// EPI: 0 = bias, 1 = bias + exact GELU, 2 = bias + residual
// ---------------------------------------------------------------------------
__device__ __forceinline__ float gelu_exact(float x) {
    return 0.5f * x * (1.0f + erff(x * 0.70710678118654752f));
}

__device__ __forceinline__ float f2tf32(float f) {
    uint32_t u;
    asm("cvt.rna.tf32.f32 %0, %1;" : "=r"(u) : "f"(f));
    return __uint_as_float(u);
}

__device__ __forceinline__ void mma_tf32(float c[4], const uint32_t a[4],
                                         const uint32_t b[2]) {
    asm volatile(
        "mma.sync.aligned.m16n8k8.row.col.f32.tf32.tf32.f32 "
        "{%0,%1,%2,%3},{%4,%5,%6,%7},{%8,%9},{%0,%1,%2,%3};\n"
        : "+f"(c[0]), "+f"(c[1]), "+f"(c[2]), "+f"(c[3])
        : "r"(a[0]), "r"(a[1]), "r"(a[2]), "r"(a[3]), "r"(b[0]), "r"(b[1]));
}

template <int EPI>
__global__ __launch_bounds__(256, 1) void gemm_tf32(const float* __restrict__ A,
                                                    const float* __restrict__ W,
                                                    const float* __restrict__ bias,
                                                    const float* __restrict__ res,
                                                    float* __restrict__ C,
                                                    int K, int Nc) {
    extern __shared__ float sm[];
    float* Abuf[2] = {sm, sm + ASTG + BSTG};
    float* Bbuf[2] = {sm + ASTG, sm + ASTG + BSTG + ASTG};

    const int tid = threadIdx.x;
    const int warp = tid >> 5, lane = tid & 31;
    const int g = lane >> 2, t = lane & 3;
    const int wm = (warp >> 1) * 32, wn = (warp & 1) * 64;
    const int brow = blockIdx.y, bcol = blockIdx.x;

    float acc[2][8][4];
#pragma unroll
    for (int i = 0; i < 2; i++)
#pragma unroll
        for (int j = 0; j < 8; j++)
#pragma unroll
            for (int c = 0; c < 4; c++) acc[i][j][c] = 0.f;

    const float* Aptr = A + (size_t)(brow * BM) * K;
    const float* Wptr = W + (size_t)bcol * BN;

    // per-thread global load coords
    const int arow[4] = {(tid + 0) >> 3, (tid + 256) >> 3, (tid + 512) >> 3,
                         (tid + 768) >> 3};
    const int acol = (tid & 7) * 4;
    const int brow4[4] = {(tid + 0) >> 5, (tid + 256) >> 5, (tid + 512) >> 5,
                          (tid + 768) >> 5};
    const int bcol4 = (tid & 31) * 4;

    float4 ar[4], br[4];
    const int nchunks = K / BK;

    // prologue: load + store chunk 0
#pragma unroll
    for (int p = 0; p < 4; p++) {
        ar[p] = *(const float4*)(Aptr + (size_t)arow[p] * K + acol);
        br[p] = *(const float4*)(Wptr + (size_t)brow4[p] * Nc + bcol4);
    }
#pragma unroll
    for (int p = 0; p < 4; p++) {
        float4 av = make_float4(f2tf32(ar[p].x), f2tf32(ar[p].y), f2tf32(ar[p].z),
                                f2tf32(ar[p].w));
        float4 bv = make_float4(f2tf32(br[p].x), f2tf32(br[p].y), f2tf32(br[p].z),
                                f2tf32(br[p].w));
        *(float4*)(Abuf[0] + arow[p] * APITCH + acol) = av;
        *(float4*)(Bbuf[0] + brow4[p] * BPITCH + bcol4) = bv;
    }
    __syncthreads();

    for (int kt = 0; kt < nchunks; kt++) {
        const int cur = kt & 1;
        if (kt + 1 < nchunks) {
            const int koff = (kt + 1) * BK;
#pragma unroll
            for (int p = 0; p < 4; p++) {
                ar[p] = *(const float4*)(Aptr + (size_t)arow[p] * K + koff + acol);
                br[p] = *(const float4*)(Wptr + (size_t)(koff + brow4[p]) * Nc + bcol4);
            }
        }

        const float* As = Abuf[cur];
        const float* Bs = Bbuf[cur];
#pragma unroll
        for (int ks = 0; ks < 4; ks++) {
            uint32_t afr[2][4], bfr[8][2];
#pragma unroll
            for (int i = 0; i < 2; i++) {
                const float* Ab = As + (wm + i * 16 + g) * APITCH + ks * 8;
                afr[i][0] = __float_as_uint(Ab[t]);
                afr[i][1] = __float_as_uint(Ab[8 * APITCH + t]);
                afr[i][2] = __float_as_uint(Ab[t + 4]);
                afr[i][3] = __float_as_uint(Ab[8 * APITCH + t + 4]);
            }
            const float* Bb = Bs + (ks * 8 + t) * BPITCH + wn + g;
#pragma unroll
            for (int j = 0; j < 8; j++) {
                bfr[j][0] = __float_as_uint(Bb[j * 8]);
                bfr[j][1] = __float_as_uint(Bb[4 * BPITCH + j * 8]);
            }
#pragma unroll
            for (int i = 0; i < 2; i++)
#pragma unroll
                for (int j = 0; j < 8; j++) mma_tf32(acc[i][j], afr[i], bfr[j]);
        }

        if (kt + 1 < nchunks) {
            const int nxt = 1 - cur;
#pragma unroll
            for (int p = 0; p < 4; p++) {
                float4 av = make_float4(f2tf32(ar[p].x), f2tf32(ar[p].y),
                                        f2tf32(ar[p].z), f2tf32(ar[p].w));
                float4 bv = make_float4(f2tf32(br[p].x), f2tf32(br[p].y),
                                        f2tf32(br[p].z), f2tf32(br[p].w));
                *(float4*)(Abuf[nxt] + arow[p] * APITCH + acol) = av;
                *(float4*)(Bbuf[nxt] + brow4[p] * BPITCH + bcol4) = bv;
            }
            __syncthreads();
        }
    }

    // Epilogue
    const int colb = bcol * BN + wn;
#pragma unroll
    for (int i = 0; i < 2; i++) {
        const size_t r0 = (size_t)(brow * BM + wm + i * 16 + g);
        const size_t r1 = r0 + 8;
#pragma unroll
        for (int j = 0; j < 8; j++) {
            const int c0 = colb + j * 8 + 2 * t;
            float2 bv = *(const float2*)(bias + c0);
            float2 o0 = make_float2(acc[i][j][0] + bv.x, acc[i][j][1] + bv.y);
            float2 o1 = make_float2(acc[i][j][2] + bv.x, acc[i][j][3] + bv.y);
            if (EPI == 1) {
                o0.x = gelu_exact(o0.x); o0.y = gelu_exact(o0.y);
                o1.x = gelu_exact(o1.x); o1.y = gelu_exact(o1.y);
            } else if (EPI == 2) {
                float2 r0v = *(const float2*)(res + r0 * Nc + c0);
                float2 r1v = *(const float2*)(res + r1 * Nc + c0);
                o0.x += r0v.x; o0.y += r0v.y;
                o1.x += r1v.x; o1.y += r1v.y;
            }
            *(float2*)(C + r0 * Nc + c0) = o0;
            *(float2*)(C + r1 * Nc + c0) = o1;
        }
    }
}

// ---------------------------------------------------------------------------
// Flash attention (fp32 SIMT) — unchanged from R2
// ---------------------------------------------------------------------------
__global__ __launch_bounds__(128) void attn_kernel(const float* __restrict__ qkv,
                                                   float* __restrict__ out) {
    extern __shared__ float smn[];
    float* Qs = smn;
    float* Ks = Qs + 64 * 65;
    float* Vs = Ks + 64 * 65;
    float* Ps = Vs + 64 * 65;

    const int bh = blockIdx.y;
    const int b = bh / HEADS, h = bh % HEADS;
    const int qblk = blockIdx.x;
    const int tid = threadIdx.x;
    const int ty = tid >> 3;
    const int tx = tid & 7;

    const float* qbase = qkv + (size_t)(b * SEQ + qblk * 64) * QKV_C + h * HEAD_DIM;
    const float* kbase = qkv + (size_t)(b * SEQ) * QKV_C + EMBED + h * HEAD_DIM;
    const float* vbase = qkv + (size_t)(b * SEQ) * QKV_C + 2 * EMBED + h * HEAD_DIM;

    for (int it = tid; it < 64 * 16; it += 128) {
        int r = it >> 4, c4 = (it & 15) * 4;
        float4 v = *(const float4*)(qbase + (size_t)r * QKV_C + c4);
        float* d = Qs + r * 65 + c4;
        d[0] = v.x; d[1] = v.y; d[2] = v.z; d[3] = v.w;
    }

    float m_i[4], l_i[4], Oacc[4][8];
#pragma unroll
    for (int i = 0; i < 4; i++) {
        m_i[i] = -INFINITY;
        l_i[i] = 0.f;
#pragma unroll
        for (int j = 0; j < 8; j++) Oacc[i][j] = 0.f;
    }
    const float scale = 0.125f;

    for (int kt = 0; kt < SEQ; kt += 64) {
        __syncthreads();
        for (int it = tid; it < 64 * 16; it += 128) {
            int r = it >> 4, c4 = (it & 15) * 4;
            float4 kv = *(const float4*)(kbase + (size_t)(kt + r) * QKV_C + c4);
            float4 vv = *(const float4*)(vbase + (size_t)(kt + r) * QKV_C + c4);
            float* kd = Ks + r * 65 + c4;
            kd[0] = kv.x; kd[1] = kv.y; kd[2] = kv.z; kd[3] = kv.w;
            float* vd = Vs + r * 65 + c4;
            vd[0] = vv.x; vd[1] = vv.y; vd[2] = vv.z; vd[3] = vv.w;
        }
        __syncthreads();

        float S[4][8];
#pragma unroll
        for (int i = 0; i < 4; i++)
#pragma unroll
            for (int j = 0; j < 8; j++) S[i][j] = 0.f;
        for (int k = 0; k < 64; k++) {
            float a[4], bb[8];
#pragma unroll
            for (int i = 0; i < 4; i++) a[i] = Qs[(ty * 4 + i) * 65 + k];
#pragma unroll
            for (int j = 0; j < 8; j++) bb[j] = Ks[(tx * 8 + j) * 65 + k];
#pragma unroll
            for (int i = 0; i < 4; i++)
#pragma unroll
                for (int j = 0; j < 8; j++)
                    S[i][j] = fmaf(a[i], bb[j], S[i][j]);
        }

        float alpha[4];
#pragma unroll
        for (int i = 0; i < 4; i++) {
            float mx = S[i][0] * scale;
#pragma unroll
            for (int j = 1; j < 8; j++) mx = fmaxf(mx, S[i][j] * scale);
#pragma unroll
            for (int o = 1; o < 8; o <<= 1)
                mx = fmaxf(mx, __shfl_xor_sync(0xffffffffu, mx, o));
            float mnew = fmaxf(m_i[i], mx);
            float sum = 0.f;
#pragma unroll
            for (int j = 0; j < 8; j++) {
                S[i][j] = __expf(S[i][j] * scale - mnew);
                sum += S[i][j];
            }
#pragma unroll
            for (int o = 1; o < 8; o <<= 1)
                sum += __shfl_xor_sync(0xffffffffu, sum, o);
            alpha[i] = __expf(m_i[i] - mnew);
            l_i[i] = l_i[i] * alpha[i] + sum;
            m_i[i] = mnew;
        }

#pragma unroll
        for (int i = 0; i < 4; i++)
#pragma unroll
            for (int j = 0; j < 8; j++)
                Ps[(ty * 4 + i) * 65 + tx * 8 + j] = S[i][j];
        __syncthreads();

#pragma unroll
        for (int i = 0; i < 4; i++)
#pragma unroll
            for (int j = 0; j < 8; j++) Oacc[i][j] *= alpha[i];
        for (int c = 0; c < 64; c++) {
            float p[4], vv[8];
#pragma unroll
            for (int i = 0; i < 4; i++) p[i] = Ps[(ty * 4 + i) * 65 + c];
#pragma unroll
            for (int j = 0; j < 8; j++) vv[j] = Vs[c * 65 + tx * 8 + j];
#pragma unroll
            for (int i = 0; i < 4; i++)
#pragma unroll
                for (int j = 0; j < 8; j++)
                    Oacc[i][j] = fmaf(p[i], vv[j], Oacc[i][j]);
        }
    }

#pragma unroll
    for (int i = 0; i < 4; i++) {
        int n = qblk * 64 + ty * 4 + i;
        float inv = 1.0f / l_i[i];
        float* op = out + (size_t)(b * SEQ + n) * EMBED + h * HEAD_DIM + tx * 8;
        float o[8];
#pragma unroll
        for (int j = 0; j < 8; j++) o[j] = Oacc[i][j] * inv;
        *(float4*)(op)     = *(float4*)(o);
        *(float4*)(op + 4) = *(float4*)(o + 4);
    }
}

// ---------------------------------------------------------------------------
extern "C" void kernel_launch(void* const* d_in, const int* in_sizes, int n_in,
                              void* d_out, int out_size) {
    const float* x      = (const float*)d_in[0];
    const float* ln1_w  = (const float*)d_in[1];
    const float* ln1_b  = (const float*)d_in[2];
    const float* ln2_w  = (const float*)d_in[3];
    const float* ln2_b  = (const float*)d_in[4];
    const float* qkv_w  = (const float*)d_in[5];
    const float* qkv_b  = (const float*)d_in[6];
    const float* proj_w = (const float*)d_in[7];
    const float* proj_b = (const float*)d_in[8];
    const float* fc1_w  = (const float*)d_in[9];
    const float* fc1_b  = (const float*)d_in[10];
    const float* fc2_w  = (const float*)d_in[11];
    const float* fc2_b  = (const float*)d_in[12];
    float* out = (float*)d_out;

    void* p;
    cudaGetSymbolAddress(&p, g_xn);  float* xn  = (float*)p;
    cudaGetSymbolAddress(&p, g_qkv); float* qkv = (float*)p;
    cudaGetSymbolAddress(&p, g_att); float* att = (float*)p;
    cudaGetSymbolAddress(&p, g_x1);  float* x1  = (float*)p;
    cudaGetSymbolAddress(&p, g_h);   float* h   = (float*)p;

    cudaFuncSetAttribute(attn_kernel, cudaFuncAttributeMaxDynamicSharedMemorySize,
                         ATTN_SMEM);
    cudaFuncSetAttribute(gemm_tf32<0>, cudaFuncAttributeMaxDynamicSharedMemorySize,
                         GEMM_SMEM);
    cudaFuncSetAttribute(gemm_tf32<1>, cudaFuncAttributeMaxDynamicSharedMemorySize,
                         GEMM_SMEM);
    cudaFuncSetAttribute(gemm_tf32<2>, cudaFuncAttributeMaxDynamicSharedMemorySize,
                         GEMM_SMEM);

    // x1 = x + proj(attn(ln1(x)))
    ln_kernel<<<ROWS, 256>>>(x, ln1_w, ln1_b, xn);
    gemm_tf32<0><<<dim3(QKV_C / BN, ROWS / BM), 256, GEMM_SMEM>>>(
        xn, qkv_w, qkv_b, nullptr, qkv, EMBED, QKV_C);
    attn_kernel<<<dim3(SEQ / 64, BATCH * HEADS), 128, ATTN_SMEM>>>(qkv, att);
    gemm_tf32<2><<<dim3(EMBED / BN, ROWS / BM), 256, GEMM_SMEM>>>(
        att, proj_w, proj_b, x, x1, EMBED, EMBED);

    // out = x1 + fc2(gelu(fc1(ln2(x1))))
    ln_kernel<<<ROWS, 256>>>(x1, ln2_w, ln2_b, xn);
    gemm_tf32<1><<<dim3(HIDDEN / BN, ROWS / BM), 256, GEMM_SMEM>>>(
        xn, fc1_w, fc1_b, nullptr, h, EMBED, HIDDEN);
    gemm_tf32<2><<<dim3(EMBED / BN, ROWS / BM), 256, GEMM_SMEM>>>(
        h, fc2_w, fc2_b, x1, out, HIDDEN, EMBED);
}

// round 4
// speedup vs baseline: 3.2458x; 2.1976x over previous
#include <cuda_runtime.h>
#include <math.h>
#include <stdint.h>

#define EMBED 1024
#define HEADS 16
#define HEAD_DIM 64
#define HIDDEN 4096
#define BATCH 2
#define SEQ 2048
#define ROWS (BATCH * SEQ)
#define QKV_C (3 * EMBED)

// ---- GEMM tiling ----
#define BM 128
#define BN 128
#define BK 16
#define STAGES 4
#define APITCH 20    // (20g+t)%32 distinct over warp -> conflict-free A frags
#define BPITCH 136   // (136t+g)%32 = (8t+g)%32 distinct -> conflict-free B frags
#define ASTG (BM * APITCH)          // 2560 floats
#define BSTG (BK * BPITCH)          // 2176 floats
#define STG_F (ASTG + BSTG)         // 4736 floats per stage
#define GEMM_SMEM (STG_F * STAGES * 4)  // 75776 B

// ---- Attention tiling ----
#define QP 68   // Q/K/P pitch: (4g+t)%32 distinct
#define VP 72   // V pitch: (8t+g)%32 distinct
#define ATTN_SMEM ((64 * QP + 64 * QP + 64 * VP) * 4)  // 53248 B

// Scratch (no cudaMalloc allowed)
__device__ float g_xn[(size_t)ROWS * EMBED];
__device__ float g_qkv[(size_t)ROWS * QKV_C];
__device__ float g_att[(size_t)ROWS * EMBED];
__device__ float g_x1[(size_t)ROWS * EMBED];
__device__ float g_h[(size_t)ROWS * HIDDEN];
__device__ float g_wqkv[(size_t)EMBED * QKV_C];
__device__ float g_wproj[(size_t)EMBED * EMBED];
__device__ float g_wfc1[(size_t)EMBED * HIDDEN];
__device__ float g_wfc2[(size_t)HIDDEN * EMBED];

// ---------------------------------------------------------------------------
__device__ __forceinline__ float f2tf32(float f) {
    uint32_t u;
    asm("cvt.rna.tf32.f32 %0, %1;" : "=r"(u) : "f"(f));
    return __uint_as_float(u);
}

__device__ __forceinline__ float gelu_exact(float x) {
    return 0.5f * x * (1.0f + erff(x * 0.70710678118654752f));
}

__device__ __forceinline__ void mma_tf32(float c[4], const uint32_t a[4],
                                         const uint32_t b[2]) {
    asm volatile(
        "mma.sync.aligned.m16n8k8.row.col.f32.tf32.tf32.f32 "
        "{%0,%1,%2,%3},{%4,%5,%6,%7},{%8,%9},{%0,%1,%2,%3};\n"
        : "+f"(c[0]), "+f"(c[1]), "+f"(c[2]), "+f"(c[3])
        : "r"(a[0]), "r"(a[1]), "r"(a[2]), "r"(a[3]), "r"(b[0]), "r"(b[1]));
}

__device__ __forceinline__ void cp16(uint32_t saddr, const void* gptr) {
    asm volatile("cp.async.cg.shared.global [%0], [%1], 16;\n" ::"r"(saddr),
                 "l"(gptr));
}

// ---------------------------------------------------------------------------
// Weight pre-conversion to tf32 (RNA) once per launch
// ---------------------------------------------------------------------------
__global__ __launch_bounds__(256) void cvt_tf32_kernel(const float* __restrict__ in,
                                                       float* __restrict__ out,
                                                       int n4) {
    int i = blockIdx.x * blockDim.x + threadIdx.x;
    if (i < n4) {
        float4 v = ((const float4*)in)[i];
        v.x = f2tf32(v.x); v.y = f2tf32(v.y);
        v.z = f2tf32(v.z); v.w = f2tf32(v.w);
        ((float4*)out)[i] = v;
    }
}

// ---------------------------------------------------------------------------
// LayerNorm (emits tf32-rounded output — consumed only as GEMM A operand)
// ---------------------------------------------------------------------------
__global__ __launch_bounds__(256) void ln_kernel(const float* __restrict__ x,
                                                 const float* __restrict__ w,
                                                 const float* __restrict__ b,
                                                 float* __restrict__ out) {
    int row = blockIdx.x;
    int t = threadIdx.x;
    const float4* xr = (const float4*)(x + (size_t)row * EMBED);
    float4 v = xr[t];
    float s = v.x + v.y + v.z + v.w;
    float q = v.x * v.x + v.y * v.y + v.z * v.z + v.w * v.w;
#pragma unroll
    for (int o = 16; o > 0; o >>= 1) {
        s += __shfl_xor_sync(0xffffffffu, s, o);
        q += __shfl_xor_sync(0xffffffffu, q, o);
    }
    __shared__ float rs[8], rq[8];
    if ((t & 31) == 0) { rs[t >> 5] = s; rq[t >> 5] = q; }
    __syncthreads();
    float ts = 0.f, tq = 0.f;
#pragma unroll
    for (int i = 0; i < 8; i++) { ts += rs[i]; tq += rq[i]; }
    float mu = ts * (1.0f / EMBED);
    float var = tq * (1.0f / EMBED) - mu * mu;
    float rstd = rsqrtf(var + 1e-5f);
    float4 wv = ((const float4*)w)[t];
    float4 bv = ((const float4*)b)[t];
    float4 o;
    o.x = f2tf32((v.x - mu) * rstd * wv.x + bv.x);
    o.y = f2tf32((v.y - mu) * rstd * wv.y + bv.y);
    o.z = f2tf32((v.z - mu) * rstd * wv.z + bv.z);
    o.w = f2tf32((v.w - mu) * rstd * wv.w + bv.w);
    ((float4*)(out + (size_t)row * EMBED))[t] = o;
}

// ---------------------------------------------------------------------------
// tf32 GEMM, cp.async 4-stage pipeline. Inputs MUST be pre-tf32-rounded.
// EPI: 0 = bias + cvt, 1 = bias + GELU + cvt, 2 = bias + residual (fp32 out)
// ---------------------------------------------------------------------------
template <int EPI>
__global__ __launch_bounds__(256, 1) void gemm_tf32(const float* __restrict__ A,
                                                    const float* __restrict__ W,
                                                    const float* __restrict__ bias,
                                                    const float* __restrict__ res,
                                                    float* __restrict__ C,
                                                    int K, int Nc) {
    extern __shared__ float sm[];
    const uint32_t sb = (uint32_t)__cvta_generic_to_shared(sm);
    const int tid = threadIdx.x;
    const int warp = tid >> 5, lane = tid & 31;
    const int g = lane >> 2, t = lane & 3;
    const int wm = (warp >> 1) * 32, wn = (warp & 1) * 64;
    const int brow = blockIdx.y, bcol = blockIdx.x;

    const float* Aptr = A + (size_t)(brow * BM) * K;
    const float* Wptr = W + (size_t)bcol * BN;

    const int ar[2] = {tid >> 2, (tid + 256) >> 2};
    const int ac = (tid & 3) * 4;
    const int brw[2] = {tid >> 5, (tid + 256) >> 5};
    const int bcl = (tid & 31) * 4;

    float acc[2][8][4];
#pragma unroll
    for (int i = 0; i < 2; i++)
#pragma unroll
        for (int j = 0; j < 8; j++)
#pragma unroll
            for (int c = 0; c < 4; c++) acc[i][j][c] = 0.f;

    const int nch = K / BK;

    auto issue = [&](int kt) {
        const int s = kt & (STAGES - 1);
        const uint32_t Asm = sb + (uint32_t)(s * STG_F) * 4u;
        const uint32_t Bsm = Asm + ASTG * 4u;
#pragma unroll
        for (int p = 0; p < 2; p++) {
            cp16(Asm + (uint32_t)(ar[p] * APITCH + ac) * 4u,
                 Aptr + (size_t)ar[p] * K + kt * BK + ac);
            cp16(Bsm + (uint32_t)(brw[p] * BPITCH + bcl) * 4u,
                 Wptr + (size_t)(kt * BK + brw[p]) * Nc + bcl);
        }
        asm volatile("cp.async.commit_group;\n");
    };

#pragma unroll
    for (int kt = 0; kt < STAGES - 1; kt++) issue(kt);

    for (int kt = 0; kt < nch; kt++) {
        asm volatile("cp.async.wait_group 2;\n");
        __syncthreads();
        if (kt + STAGES - 1 < nch) issue(kt + STAGES - 1);

        const int s = kt & (STAGES - 1);
        const float* As = sm + s * STG_F;
        const float* Bs = As + ASTG;
#pragma unroll
        for (int ks = 0; ks < 2; ks++) {
            uint32_t afr[2][4], bfr[8][2];
#pragma unroll
            for (int i = 0; i < 2; i++) {
                const float* Ab = As + (wm + i * 16 + g) * APITCH + ks * 8;
                afr[i][0] = __float_as_uint(Ab[t]);
                afr[i][1] = __float_as_uint(Ab[8 * APITCH + t]);
                afr[i][2] = __float_as_uint(Ab[t + 4]);
                afr[i][3] = __float_as_uint(Ab[8 * APITCH + t + 4]);
            }
            const float* Bb = Bs + (ks * 8 + t) * BPITCH + wn + g;
#pragma unroll
            for (int j = 0; j < 8; j++) {
                bfr[j][0] = __float_as_uint(Bb[j * 8]);
                bfr[j][1] = __float_as_uint(Bb[4 * BPITCH + j * 8]);
            }
#pragma unroll
            for (int i = 0; i < 2; i++)
#pragma unroll
                for (int j = 0; j < 8; j++) mma_tf32(acc[i][j], afr[i], bfr[j]);
        }
    }

    // Epilogue
    const int colb = bcol * BN + wn;
#pragma unroll
    for (int i = 0; i < 2; i++) {
        const size_t r0 = (size_t)(brow * BM + wm + i * 16 + g);
        const size_t r1 = r0 + 8;
#pragma unroll
        for (int j = 0; j < 8; j++) {
            const int c0 = colb + j * 8 + 2 * t;
            float2 bv = *(const float2*)(bias + c0);
            float2 o0 = make_float2(acc[i][j][0] + bv.x, acc[i][j][1] + bv.y);
            float2 o1 = make_float2(acc[i][j][2] + bv.x, acc[i][j][3] + bv.y);
            if (EPI == 0) {
                o0.x = f2tf32(o0.x); o0.y = f2tf32(o0.y);
                o1.x = f2tf32(o1.x); o1.y = f2tf32(o1.y);
            } else if (EPI == 1) {
                o0.x = f2tf32(gelu_exact(o0.x)); o0.y = f2tf32(gelu_exact(o0.y));
                o1.x = f2tf32(gelu_exact(o1.x)); o1.y = f2tf32(gelu_exact(o1.y));
            } else {
                float2 r0v = *(const float2*)(res + r0 * Nc + c0);
                float2 r1v = *(const float2*)(res + r1 * Nc + c0);
                o0.x += r0v.x; o0.y += r0v.y;
                o1.x += r1v.x; o1.y += r1v.y;
            }
            *(float2*)(C + r0 * Nc + c0) = o0;
            *(float2*)(C + r1 * Nc + c0) = o1;
        }
    }
}

// ---------------------------------------------------------------------------
// Tensor-core flash attention (tf32). 4 warps, 64 q-rows/block, 64-key tiles.
// qkv buffer is already tf32-rounded. Output is tf32-rounded (feeds proj A).
// ---------------------------------------------------------------------------
__global__ __launch_bounds__(128) void attn_mma(const float* __restrict__ qkv,
                                                float* __restrict__ out) {
    extern __shared__ float sma[];
    float* Qs = sma;                // [64][QP]; becomes per-warp P after Q->regs
    float* Ks = Qs + 64 * QP;       // [64][QP]
    float* Vs = Ks + 64 * QP;       // [64][VP]

    const int bh = blockIdx.y;
    const int b = bh >> 4, h = bh & 15;
    const int qblk = blockIdx.x;
    const int tid = threadIdx.x;
    const int w = tid >> 5, lane = tid & 31;
    const int g = lane >> 2, t = lane & 3;
    const int wm = w * 16;

    const float* qbase = qkv + (size_t)(b * SEQ + qblk * 64) * QKV_C + h * HEAD_DIM;
    const float* kbase = qkv + (size_t)(b * SEQ) * QKV_C + EMBED + h * HEAD_DIM;
    const float* vbase = qkv + (size_t)(b * SEQ) * QKV_C + 2 * EMBED + h * HEAD_DIM;

    // Load Q tile to smem (coalesced), then to registers (pre-scaled, exact x2^-3)
    for (int it = tid; it < 64 * 16; it += 128) {
        int r = it >> 4, c4 = (it & 15) * 4;
        *(float4*)(Qs + r * QP + c4) =
            *(const float4*)(qbase + (size_t)r * QKV_C + c4);
    }
    __syncthreads();

    uint32_t qa[8][4];
    float* Pw = Qs + wm * QP;  // warp-private region (its own Q rows)
#pragma unroll
    for (int kk = 0; kk < 8; kk++) {
        qa[kk][0] = __float_as_uint(0.125f * Pw[g * QP + kk * 8 + t]);
        qa[kk][1] = __float_as_uint(0.125f * Pw[(g + 8) * QP + kk * 8 + t]);
        qa[kk][2] = __float_as_uint(0.125f * Pw[g * QP + kk * 8 + t + 4]);
        qa[kk][3] = __float_as_uint(0.125f * Pw[(g + 8) * QP + kk * 8 + t + 4]);
    }

    float m0 = -INFINITY, m1 = -INFINITY, l0 = 0.f, l1 = 0.f;
    float o[8][4];
#pragma unroll
    for (int j = 0; j < 8; j++)
#pragma unroll
        for (int c = 0; c < 4; c++) o[j][c] = 0.f;

    for (int kt = 0; kt < SEQ; kt += 64) {
        __syncthreads();
        for (int it = tid; it < 64 * 16; it += 128) {
            int r = it >> 4, c4 = (it & 15) * 4;
            *(float4*)(Ks + r * QP + c4) =
                *(const float4*)(kbase + (size_t)(kt + r) * QKV_C + c4);
            *(float4*)(Vs + r * VP + c4) =
                *(const float4*)(vbase + (size_t)(kt + r) * QKV_C + c4);
        }
        __syncthreads();

        // S = (Q*scale) @ K^T
        float sacc[8][4];
#pragma unroll
        for (int j = 0; j < 8; j++)
#pragma unroll
            for (int c = 0; c < 4; c++) sacc[j][c] = 0.f;
#pragma unroll
        for (int kk = 0; kk < 8; kk++) {
            uint32_t bf[8][2];
#pragma unroll
            for (int j = 0; j < 8; j++) {
                const float* Kb = Ks + (j * 8 + g) * QP + kk * 8 + t;
                bf[j][0] = __float_as_uint(Kb[0]);
                bf[j][1] = __float_as_uint(Kb[4]);
            }
#pragma unroll
            for (int j = 0; j < 8; j++) mma_tf32(sacc[j], qa[kk], bf[j]);
        }

        // Online softmax (rows g and g+8; reduce over quad lanes t)
        float mx0 = -INFINITY, mx1 = -INFINITY;
#pragma unroll
        for (int j = 0; j < 8; j++) {
            mx0 = fmaxf(mx0, fmaxf(sacc[j][0], sacc[j][1]));
            mx1 = fmaxf(mx1, fmaxf(sacc[j][2], sacc[j][3]));
        }
#pragma unroll
        for (int off = 1; off < 4; off <<= 1) {
            mx0 = fmaxf(mx0, __shfl_xor_sync(0xffffffffu, mx0, off));
            mx1 = fmaxf(mx1, __shfl_xor_sync(0xffffffffu, mx1, off));
        }
        float mn0 = fmaxf(m0, mx0), mn1 = fmaxf(m1, mx1);
        float a0 = __expf(m0 - mn0), a1 = __expf(m1 - mn1);
        float s0 = 0.f, s1 = 0.f;
#pragma unroll
        for (int j = 0; j < 8; j++) {
            float p0 = f2tf32(__expf(sacc[j][0] - mn0));
            float p1 = f2tf32(__expf(sacc[j][1] - mn0));
            float p2 = f2tf32(__expf(sacc[j][2] - mn1));
            float p3 = f2tf32(__expf(sacc[j][3] - mn1));
            s0 += p0 + p1; s1 += p2 + p3;
            *(float2*)(Pw + g * QP + j * 8 + 2 * t) = make_float2(p0, p1);
            *(float2*)(Pw + (g + 8) * QP + j * 8 + 2 * t) = make_float2(p2, p3);
        }
#pragma unroll
        for (int off = 1; off < 4; off <<= 1) {
            s0 += __shfl_xor_sync(0xffffffffu, s0, off);
            s1 += __shfl_xor_sync(0xffffffffu, s1, off);
        }
        l0 = l0 * a0 + s0; l1 = l1 * a1 + s1;
        m0 = mn0; m1 = mn1;
#pragma unroll
        for (int j = 0; j < 8; j++) {
            o[j][0] *= a0; o[j][1] *= a0; o[j][2] *= a1; o[j][3] *= a1;
        }
        __syncwarp();

        // O += P @ V
#pragma unroll
        for (int kk = 0; kk < 8; kk++) {
            uint32_t pa[4];
            pa[0] = __float_as_uint(Pw[g * QP + kk * 8 + t]);
            pa[1] = __float_as_uint(Pw[(g + 8) * QP + kk * 8 + t]);
            pa[2] = __float_as_uint(Pw[g * QP + kk * 8 + t + 4]);
            pa[3] = __float_as_uint(Pw[(g + 8) * QP + kk * 8 + t + 4]);
            uint32_t bf[8][2];
#pragma unroll
            for (int j = 0; j < 8; j++) {
                bf[j][0] = __float_as_uint(Vs[(kk * 8 + t) * VP + j * 8 + g]);
                bf[j][1] = __float_as_uint(Vs[(kk * 8 + t + 4) * VP + j * 8 + g]);
            }
#pragma unroll
            for (int j = 0; j < 8; j++) mma_tf32(o[j], pa, bf[j]);
        }
    }

    // Epilogue: normalize, tf32-round (feeds proj GEMM A), store
    float inv0 = 1.f / l0, inv1 = 1.f / l1;
    const int row0 = qblk * 64 + wm + g;
    float* ob = out + (size_t)(b * SEQ) * EMBED + h * HEAD_DIM;
#pragma unroll
    for (int j = 0; j < 8; j++) {
        float2 v0 = make_float2(f2tf32(o[j][0] * inv0), f2tf32(o[j][1] * inv0));
        float2 v1 = make_float2(f2tf32(o[j][2] * inv1), f2tf32(o[j][3] * inv1));
        *(float2*)(ob + (size_t)row0 * EMBED + j * 8 + 2 * t) = v0;
        *(float2*)(ob + (size_t)(row0 + 8) * EMBED + j * 8 + 2 * t) = v1;
    }
}

// ---------------------------------------------------------------------------
extern "C" void kernel_launch(void* const* d_in, const int* in_sizes, int n_in,
                              void* d_out, int out_size) {
    const float* x      = (const float*)d_in[0];
    const float* ln1_w  = (const float*)d_in[1];
    const float* ln1_b  = (const float*)d_in[2];
    const float* ln2_w  = (const float*)d_in[3];
    const float* ln2_b  = (const float*)d_in[4];
    const float* qkv_w  = (const float*)d_in[5];
    const float* qkv_b  = (const float*)d_in[6];
    const float* proj_w = (const float*)d_in[7];
    const float* proj_b = (const float*)d_in[8];
    const float* fc1_w  = (const float*)d_in[9];
    const float* fc1_b  = (const float*)d_in[10];
    const float* fc2_w  = (const float*)d_in[11];
    const float* fc2_b  = (const float*)d_in[12];
    float* out = (float*)d_out;

    void* p;
    cudaGetSymbolAddress(&p, g_xn);    float* xn  = (float*)p;
    cudaGetSymbolAddress(&p, g_qkv);   float* qkv = (float*)p;
    cudaGetSymbolAddress(&p, g_att);   float* att = (float*)p;
    cudaGetSymbolAddress(&p, g_x1);    float* x1  = (float*)p;
    cudaGetSymbolAddress(&p, g_h);     float* h   = (float*)p;
    cudaGetSymbolAddress(&p, g_wqkv);  float* wqkv  = (float*)p;
    cudaGetSymbolAddress(&p, g_wproj); float* wproj = (float*)p;
    cudaGetSymbolAddress(&p, g_wfc1);  float* wfc1  = (float*)p;
    cudaGetSymbolAddress(&p, g_wfc2);  float* wfc2  = (float*)p;

    cudaFuncSetAttribute(attn_mma, cudaFuncAttributeMaxDynamicSharedMemorySize,
                         ATTN_SMEM);
    cudaFuncSetAttribute(gemm_tf32<0>, cudaFuncAttributeMaxDynamicSharedMemorySize,
                         GEMM_SMEM);
    cudaFuncSetAttribute(gemm_tf32<1>, cudaFuncAttributeMaxDynamicSharedMemorySize,
                         GEMM_SMEM);
    cudaFuncSetAttribute(gemm_tf32<2>, cudaFuncAttributeMaxDynamicSharedMemorySize,
                         GEMM_SMEM);

    // Pre-round weights to tf32 (RNA)
    cvt_tf32_kernel<<<(EMBED * QKV_C / 4 + 255) / 256, 256>>>(qkv_w, wqkv,
                                                              EMBED * QKV_C / 4);
    cvt_tf32_kernel<<<(EMBED * EMBED / 4 + 255) / 256, 256>>>(proj_w, wproj,
                                                              EMBED * EMBED / 4);
    cvt_tf32_kernel<<<(EMBED * HIDDEN / 4 + 255) / 256, 256>>>(fc1_w, wfc1,
                                                               EMBED * HIDDEN / 4);
    cvt_tf32_kernel<<<(HIDDEN * EMBED / 4 + 255) / 256, 256>>>(fc2_w, wfc2,
                                                               HIDDEN * EMBED / 4);

    // x1 = x + proj(attn(ln1(x)))
    ln_kernel<<<ROWS, 256>>>(x, ln1_w, ln1_b, xn);
    gemm_tf32<0><<<dim3(QKV_C / BN, ROWS / BM), 256, GEMM_SMEM>>>(
        xn, wqkv, qkv_b, nullptr, qkv, EMBED, QKV_C);
    attn_mma<<<dim3(SEQ / 64, BATCH * HEADS), 128, ATTN_SMEM>>>(qkv, att);
    gemm_tf32<2><<<dim3(EMBED / BN, ROWS / BM), 256, GEMM_SMEM>>>(
        att, wproj, proj_b, x, x1, EMBED, EMBED);

    // out = x1 + fc2(gelu(fc1(ln2(x1))))
    ln_kernel<<<ROWS, 256>>>(x1, ln2_w, ln2_b, xn);
    gemm_tf32<1><<<dim3(HIDDEN / BN, ROWS / BM), 256, GEMM_SMEM>>>(
        xn, wfc1, fc1_b, nullptr, h, EMBED, HIDDEN);
    gemm_tf32<2><<<dim3(EMBED / BN, ROWS / BM), 256, GEMM_SMEM>>>(
        h, wfc2, fc2_b, x1, out, HIDDEN, EMBED);
}

// round 6
// speedup vs baseline: 3.6104x; 1.1124x over previous
#include <cuda_runtime.h>
#include <math.h>
#include <stdint.h>

#define EMBED 1024
#define HEADS 16
#define HEAD_DIM 64
#define HIDDEN 4096
#define BATCH 2
#define SEQ 2048
#define ROWS (BATCH * SEQ)
#define QKV_C (3 * EMBED)

// ---- GEMM tiling ----
#define BM 128
#define BN 128
#define BK 32
#define STAGES 3
#define APITCH 36    // (36g+t)%32=(4g+t)%32 distinct -> conflict-free A frags
#define BPITCH 136   // (136t+g)%32=(8t+g)%32 distinct -> conflict-free B frags
#define ASTG (BM * APITCH)          // 4608 floats
#define BSTG (BK * BPITCH)          // 4352 floats
#define STG_F (ASTG + BSTG)         // 8960 floats per stage
#define GEMM_SMEM (STG_F * STAGES * 4)  // 107520 B

// ---- Attention tiling ----
#define QP 68   // Q/K/P pitch
#define VP 72   // V pitch
#define KVSTG (64 * QP + 64 * VP)   // 8960 floats per K/V stage
#define ATTN_SMEM ((64 * QP + 2 * KVSTG) * 4)  // 89088 B

// Scratch (no cudaMalloc allowed)
__device__ float g_xn[(size_t)ROWS * EMBED];
__device__ float g_qkv[(size_t)ROWS * QKV_C];
__device__ float g_att[(size_t)ROWS * EMBED];
__device__ float g_x1[(size_t)ROWS * EMBED];
__device__ float g_h[(size_t)ROWS * HIDDEN];
__device__ float g_wqkv[(size_t)EMBED * QKV_C];
__device__ float g_wproj[(size_t)EMBED * EMBED];
__device__ float g_wfc1[(size_t)EMBED * HIDDEN];
__device__ float g_wfc2[(size_t)HIDDEN * EMBED];

// ---------------------------------------------------------------------------
__device__ __forceinline__ float f2tf32(float f) {
    uint32_t u;
    asm("cvt.rna.tf32.f32 %0, %1;" : "=r"(u) : "f"(f));
    return __uint_as_float(u);
}

__device__ __forceinline__ float gelu_exact(float x) {
    return 0.5f * x * (1.0f + erff(x * 0.70710678118654752f));
}

__device__ __forceinline__ void mma_tf32(float c[4], const uint32_t a[4],
                                         const uint32_t b[2]) {
    asm volatile(
        "mma.sync.aligned.m16n8k8.row.col.f32.tf32.tf32.f32 "
        "{%0,%1,%2,%3},{%4,%5,%6,%7},{%8,%9},{%0,%1,%2,%3};\n"
        : "+f"(c[0]), "+f"(c[1]), "+f"(c[2]), "+f"(c[3])
        : "r"(a[0]), "r"(a[1]), "r"(a[2]), "r"(a[3]), "r"(b[0]), "r"(b[1]));
}

__device__ __forceinline__ void cp16(uint32_t saddr, const void* gptr) {
    asm volatile("cp.async.cg.shared.global [%0], [%1], 16;\n" ::"r"(saddr),
                 "l"(gptr));
}

// ---------------------------------------------------------------------------
// Weight pre-conversion to tf32 (RNA) once per launch
// ---------------------------------------------------------------------------
__global__ __launch_bounds__(256) void cvt_tf32_kernel(const float* __restrict__ in,
                                                       float* __restrict__ out,
                                                       int n4) {
    int i = blockIdx.x * blockDim.x + threadIdx.x;
    if (i < n4) {
        float4 v = ((const float4*)in)[i];
        v.x = f2tf32(v.x); v.y = f2tf32(v.y);
        v.z = f2tf32(v.z); v.w = f2tf32(v.w);
        ((float4*)out)[i] = v;
    }
}

// ---------------------------------------------------------------------------
// LayerNorm (emits tf32-rounded output — consumed only as GEMM A operand)
// ---------------------------------------------------------------------------
__global__ __launch_bounds__(256) void ln_kernel(const float* __restrict__ x,
                                                 const float* __restrict__ w,
                                                 const float* __restrict__ b,
                                                 float* __restrict__ out) {
    int row = blockIdx.x;
    int t = threadIdx.x;
    const float4* xr = (const float4*)(x + (size_t)row * EMBED);
    float4 v = xr[t];
    float s = v.x + v.y + v.z + v.w;
    float q = v.x * v.x + v.y * v.y + v.z * v.z + v.w * v.w;
#pragma unroll
    for (int o = 16; o > 0; o >>= 1) {
        s += __shfl_xor_sync(0xffffffffu, s, o);
        q += __shfl_xor_sync(0xffffffffu, q, o);
    }
    __shared__ float rs[8], rq[8];
    if ((t & 31) == 0) { rs[t >> 5] = s; rq[t >> 5] = q; }
    __syncthreads();
    float ts = 0.f, tq = 0.f;
#pragma unroll
    for (int i = 0; i < 8; i++) { ts += rs[i]; tq += rq[i]; }
    float mu = ts * (1.0f / EMBED);
    float var = tq * (1.0f / EMBED) - mu * mu;
    float rstd = rsqrtf(var + 1e-5f);
    float4 wv = ((const float4*)w)[t];
    float4 bv = ((const float4*)b)[t];
    float4 o;
    o.x = f2tf32((v.x - mu) * rstd * wv.x + bv.x);
    o.y = f2tf32((v.y - mu) * rstd * wv.y + bv.y);
    o.z = f2tf32((v.z - mu) * rstd * wv.z + bv.z);
    o.w = f2tf32((v.w - mu) * rstd * wv.w + bv.w);
    ((float4*)(out + (size_t)row * EMBED))[t] = o;
}

// ---------------------------------------------------------------------------
// tf32 GEMM, cp.async 3-stage pipeline, BK=32. Inputs pre-tf32-rounded.
// EPI: 0 = bias + cvt, 1 = bias + GELU + cvt, 2 = bias + residual (fp32 out)
// ---------------------------------------------------------------------------
template <int EPI>
__global__ __launch_bounds__(256, 1) void gemm_tf32(const float* __restrict__ A,
                                                    const float* __restrict__ W,
                                                    const float* __restrict__ bias,
                                                    const float* __restrict__ res,
                                                    float* __restrict__ C,
                                                    int K, int Nc) {
    extern __shared__ float sm[];
    const uint32_t sb = (uint32_t)__cvta_generic_to_shared(sm);
    const int tid = threadIdx.x;
    const int warp = tid >> 5, lane = tid & 31;
    const int g = lane >> 2, t = lane & 3;
    const int wm = (warp >> 1) * 32, wn = (warp & 1) * 64;
    const int brow = blockIdx.y, bcol = blockIdx.x;

    const float* Aptr = A + (size_t)(brow * BM) * K;
    const float* Wptr = W + (size_t)bcol * BN;

    // A: 128 rows x 32 cols. 8 threads/row, 4 row-passes.
    const int arow = tid >> 3;          // 0..31, +32*i
    const int acol = (tid & 7) * 4;
    // B: 32 rows x 128 cols. 32 threads/row, 4 row-passes.
    const int brw = tid >> 5;           // 0..7, +8*i
    const int bcl = (tid & 31) * 4;

    float acc[2][8][4];
#pragma unroll
    for (int i = 0; i < 2; i++)
#pragma unroll
        for (int j = 0; j < 8; j++)
#pragma unroll
            for (int c = 0; c < 4; c++) acc[i][j][c] = 0.f;

    const int nch = K / BK;

    auto issue = [&](int kt) {
        const int s = kt % STAGES;
        const uint32_t Asm = sb + (uint32_t)(s * STG_F) * 4u;
        const uint32_t Bsm = Asm + ASTG * 4u;
#pragma unroll
        for (int i = 0; i < 4; i++) {
            const int r = arow + 32 * i;
            cp16(Asm + (uint32_t)(r * APITCH + acol) * 4u,
                 Aptr + (size_t)r * K + kt * BK + acol);
        }
#pragma unroll
        for (int i = 0; i < 4; i++) {
            const int r = brw + 8 * i;
            cp16(Bsm + (uint32_t)(r * BPITCH + bcl) * 4u,
                 Wptr + (size_t)(kt * BK + r) * Nc + bcl);
        }
    };

    issue(0);
    asm volatile("cp.async.commit_group;" ::: "memory");
    issue(1);
    asm volatile("cp.async.commit_group;" ::: "memory");

    for (int kt = 0; kt < nch; kt++) {
        asm volatile("cp.async.wait_group 1;" ::: "memory");
        __syncthreads();

        const int s = kt % STAGES;
        const float* As = sm + s * STG_F;
        const float* Bs = As + ASTG;
#pragma unroll
        for (int ks = 0; ks < 4; ks++) {
            uint32_t afr[2][4], bfr[8][2];
#pragma unroll
            for (int i = 0; i < 2; i++) {
                const float* Ab = As + (wm + i * 16 + g) * APITCH + ks * 8;
                afr[i][0] = __float_as_uint(Ab[t]);
                afr[i][1] = __float_as_uint(Ab[8 * APITCH + t]);
                afr[i][2] = __float_as_uint(Ab[t + 4]);
                afr[i][3] = __float_as_uint(Ab[8 * APITCH + t + 4]);
            }
            const float* Bb = Bs + (ks * 8 + t) * BPITCH + wn + g;
#pragma unroll
            for (int j = 0; j < 8; j++) {
                bfr[j][0] = __float_as_uint(Bb[j * 8]);
                bfr[j][1] = __float_as_uint(Bb[4 * BPITCH + j * 8]);
            }
#pragma unroll
            for (int i = 0; i < 2; i++)
#pragma unroll
                for (int j = 0; j < 8; j++) mma_tf32(acc[i][j], afr[i], bfr[j]);
        }

        if (kt + 2 < nch) issue(kt + 2);
        asm volatile("cp.async.commit_group;" ::: "memory");
    }

    // Epilogue
    const int colb = bcol * BN + wn;
#pragma unroll
    for (int i = 0; i < 2; i++) {
        const size_t r0 = (size_t)(brow * BM + wm + i * 16 + g);
        const size_t r1 = r0 + 8;
#pragma unroll
        for (int j = 0; j < 8; j++) {
            const int c0 = colb + j * 8 + 2 * t;
            float2 bv = *(const float2*)(bias + c0);
            float2 o0 = make_float2(acc[i][j][0] + bv.x, acc[i][j][1] + bv.y);
            float2 o1 = make_float2(acc[i][j][2] + bv.x, acc[i][j][3] + bv.y);
            if (EPI == 0) {
                o0.x = f2tf32(o0.x); o0.y = f2tf32(o0.y);
                o1.x = f2tf32(o1.x); o1.y = f2tf32(o1.y);
            } else if (EPI == 1) {
                o0.x = f2tf32(gelu_exact(o0.x)); o0.y = f2tf32(gelu_exact(o0.y));
                o1.x = f2tf32(gelu_exact(o1.x)); o1.y = f2tf32(gelu_exact(o1.y));
            } else {
                float2 r0v = *(const float2*)(res + r0 * Nc + c0);
                float2 r1v = *(const float2*)(res + r1 * Nc + c0);
                o0.x += r0v.x; o0.y += r0v.y;
                o1.x += r1v.x; o1.y += r1v.y;
            }
            *(float2*)(C + r0 * Nc + c0) = o0;
            *(float2*)(C + r1 * Nc + c0) = o1;
        }
    }
}

// ---------------------------------------------------------------------------
// Tensor-core flash attention (tf32), cp.async double-buffered K/V tiles.
// 4 warps, 64 q-rows/block, 64-key tiles. qkv pre-tf32-rounded; output
// tf32-rounded (feeds proj GEMM A).
// ---------------------------------------------------------------------------
__global__ __launch_bounds__(128) void attn_mma(const float* __restrict__ qkv,
                                                float* __restrict__ out) {
    extern __shared__ float sma[];
    float* Qs = sma;  // [64][QP]; per-warp sub-blocks double as P staging
    const uint32_t sb = (uint32_t)__cvta_generic_to_shared(sma);
    const uint32_t kvb = sb + 64 * QP * 4;  // two K/V stages follow Q

    const int bh = blockIdx.y;
    const int b = bh >> 4, h = bh & 15;
    const int qblk = blockIdx.x;
    const int tid = threadIdx.x;
    const int w = tid >> 5, lane = tid & 31;
    const int g = lane >> 2, t = lane & 3;
    const int wm = w * 16;

    const float* qbase = qkv + (size_t)(b * SEQ + qblk * 64) * QKV_C + h * HEAD_DIM;
    const float* kbase = qkv + (size_t)(b * SEQ) * QKV_C + EMBED + h * HEAD_DIM;
    const float* vbase = qkv + (size_t)(b * SEQ) * QKV_C + 2 * EMBED + h * HEAD_DIM;

    // K/V tile loader: tile tt -> stage buffer s
    const int lr = tid >> 4;           // 0..7, +8*i
    const int lc = (tid & 15) * 4;
    auto issue_kv = [&](int tt, int s) {
        const uint32_t kd = kvb + (uint32_t)(s * KVSTG) * 4u;
        const uint32_t vd = kd + 64 * QP * 4u;
        const float* kp = kbase + (size_t)(tt * 64) * QKV_C;
        const float* vp = vbase + (size_t)(tt * 64) * QKV_C;
#pragma unroll
        for (int i = 0; i < 8; i++) {
            const int r = lr + 8 * i;
            cp16(kd + (uint32_t)(r * QP + lc) * 4u, kp + (size_t)r * QKV_C + lc);
            cp16(vd + (uint32_t)(r * VP + lc) * 4u, vp + (size_t)r * QKV_C + lc);
        }
    };

    issue_kv(0, 0);
    asm volatile("cp.async.commit_group;" ::: "memory");
    issue_kv(1, 1);
    asm volatile("cp.async.commit_group;" ::: "memory");

    // Load Q tile to smem, then into registers (pre-scaled by 1/8, exact)
    for (int it = tid; it < 64 * 16; it += 128) {
        int r = it >> 4, c4 = (it & 15) * 4;
        *(float4*)(Qs + r * QP + c4) =
            *(const float4*)(qbase + (size_t)r * QKV_C + c4);
    }
    __syncthreads();

    uint32_t qa[8][4];
    float* Pw = Qs + wm * QP;  // warp-private region (its own Q rows)
#pragma unroll
    for (int kk = 0; kk < 8; kk++) {
        qa[kk][0] = __float_as_uint(0.125f * Pw[g * QP + kk * 8 + t]);
        qa[kk][1] = __float_as_uint(0.125f * Pw[(g + 8) * QP + kk * 8 + t]);
        qa[kk][2] = __float_as_uint(0.125f * Pw[g * QP + kk * 8 + t + 4]);
        qa[kk][3] = __float_as_uint(0.125f * Pw[(g + 8) * QP + kk * 8 + t + 4]);
    }

    float m0 = -INFINITY, m1 = -INFINITY, l0 = 0.f, l1 = 0.f;
    float o[8][4];
#pragma unroll
    for (int j = 0; j < 8; j++)
#pragma unroll
        for (int c = 0; c < 4; c++) o[j][c] = 0.f;

    const int ntiles = SEQ / 64;
    for (int it = 0; it < ntiles; it++) {
        asm volatile("cp.async.wait_group 1;" ::: "memory");
        __syncthreads();

        const int s = it & 1;
        const float* Ks = sma + 64 * QP + s * KVSTG;
        const float* Vs = Ks + 64 * QP;

        // S = (Q*scale) @ K^T
        float sacc[8][4];
#pragma unroll
        for (int j = 0; j < 8; j++)
#pragma unroll
            for (int c = 0; c < 4; c++) sacc[j][c] = 0.f;
#pragma unroll
        for (int kk = 0; kk < 8; kk++) {
            uint32_t bf[8][2];
#pragma unroll
            for (int j = 0; j < 8; j++) {
                const float* Kb = Ks + (j * 8 + g) * QP + kk * 8 + t;
                bf[j][0] = __float_as_uint(Kb[0]);
                bf[j][1] = __float_as_uint(Kb[4]);
            }
#pragma unroll
            for (int j = 0; j < 8; j++) mma_tf32(sacc[j], qa[kk], bf[j]);
        }

        // Online softmax (rows g and g+8; reduce over quad lanes t)
        float mx0 = -INFINITY, mx1 = -INFINITY;
#pragma unroll
        for (int j = 0; j < 8; j++) {
            mx0 = fmaxf(mx0, fmaxf(sacc[j][0], sacc[j][1]));
            mx1 = fmaxf(mx1, fmaxf(sacc[j][2], sacc[j][3]));
        }
#pragma unroll
        for (int off = 1; off < 4; off <<= 1) {
            mx0 = fmaxf(mx0, __shfl_xor_sync(0xffffffffu, mx0, off));
            mx1 = fmaxf(mx1, __shfl_xor_sync(0xffffffffu, mx1, off));
        }
        float mn0 = fmaxf(m0, mx0), mn1 = fmaxf(m1, mx1);
        float a0 = __expf(m0 - mn0), a1 = __expf(m1 - mn1);
        float s0 = 0.f, s1 = 0.f;
#pragma unroll
        for (int j = 0; j < 8; j++) {
            float p0 = f2tf32(__expf(sacc[j][0] - mn0));
            float p1 = f2tf32(__expf(sacc[j][1] - mn0));
            float p2 = f2tf32(__expf(sacc[j][2] - mn1));
            float p3 = f2tf32(__expf(sacc[j][3] - mn1));
            s0 += p0 + p1; s1 += p2 + p3;
            *(float2*)(Pw + g * QP + j * 8 + 2 * t) = make_float2(p0, p1);
            *(float2*)(Pw + (g + 8) * QP + j * 8 + 2 * t) = make_float2(p2, p3);
        }
#pragma unroll
        for (int off = 1; off < 4; off <<= 1) {
            s0 += __shfl_xor_sync(0xffffffffu, s0, off);
            s1 += __shfl_xor_sync(0xffffffffu, s1, off);
        }
        l0 = l0 * a0 + s0; l1 = l1 * a1 + s1;
        m0 = mn0; m1 = mn1;
#pragma unroll
        for (int j = 0; j < 8; j++) {
            o[j][0] *= a0; o[j][1] *= a0; o[j][2] *= a1; o[j][3] *= a1;
        }
        __syncwarp();

        // O += P @ V
#pragma unroll
        for (int kk = 0; kk < 8; kk++) {
            uint32_t pa[4];
            pa[0] = __float_as_uint(Pw[g * QP + kk * 8 + t]);
            pa[1] = __float_as_uint(Pw[(g + 8) * QP + kk * 8 + t]);
            pa[2] = __float_as_uint(Pw[g * QP + kk * 8 + t + 4]);
            pa[3] = __float_as_uint(Pw[(g + 8) * QP + kk * 8 + t + 4]);
            uint32_t bf[8][2];
#pragma unroll
            for (int j = 0; j < 8; j++) {
                bf[j][0] = __float_as_uint(Vs[(kk * 8 + t) * VP + j * 8 + g]);
                bf[j][1] = __float_as_uint(Vs[(kk * 8 + t + 4) * VP + j * 8 + g]);
            }
#pragma unroll
            for (int j = 0; j < 8; j++) mma_tf32(o[j], pa, bf[j]);
        }

        // Refill the stage we just consumed with tile it+2
        __syncthreads();
        if (it + 2 < ntiles) issue_kv(it + 2, s);
        asm volatile("cp.async.commit_group;" ::: "memory");
    }

    // Epilogue: normalize, tf32-round (feeds proj GEMM A), store
    float inv0 = 1.f / l0, inv1 = 1.f / l1;
    const int row0 = qblk * 64 + wm + g;
    float* ob = out + (size_t)(b * SEQ) * EMBED + h * HEAD_DIM;
#pragma unroll
    for (int j = 0; j < 8; j++) {
        float2 v0 = make_float2(f2tf32(o[j][0] * inv0), f2tf32(o[j][1] * inv0));
        float2 v1 = make_float2(f2tf32(o[j][2] * inv1), f2tf32(o[j][3] * inv1));
        *(float2*)(ob + (size_t)row0 * EMBED + j * 8 + 2 * t) = v0;
        *(float2*)(ob + (size_t)(row0 + 8) * EMBED + j * 8 + 2 * t) = v1;
    }
}

// ---------------------------------------------------------------------------
extern "C" void kernel_launch(void* const* d_in, const int* in_sizes, int n_in,
                              void* d_out, int out_size) {
    const float* x      = (const float*)d_in[0];
    const float* ln1_w  = (const float*)d_in[1];
    const float* ln1_b  = (const float*)d_in[2];
    const float* ln2_w  = (const float*)d_in[3];
    const float* ln2_b  = (const float*)d_in[4];
    const float* qkv_w  = (const float*)d_in[5];
    const float* qkv_b  = (const float*)d_in[6];
    const float* proj_w = (const float*)d_in[7];
    const float* proj_b = (const float*)d_in[8];
    const float* fc1_w  = (const float*)d_in[9];
    const float* fc1_b  = (const float*)d_in[10];
    const float* fc2_w  = (const float*)d_in[11];
    const float* fc2_b  = (const float*)d_in[12];
    float* out = (float*)d_out;

    void* p;
    cudaGetSymbolAddress(&p, g_xn);    float* xn  = (float*)p;
    cudaGetSymbolAddress(&p, g_qkv);   float* qkv = (float*)p;
    cudaGetSymbolAddress(&p, g_att);   float* att = (float*)p;
    cudaGetSymbolAddress(&p, g_x1);    float* x1  = (float*)p;
    cudaGetSymbolAddress(&p, g_h);     float* h   = (float*)p;
    cudaGetSymbolAddress(&p, g_wqkv);  float* wqkv  = (float*)p;
    cudaGetSymbolAddress(&p, g_wproj); float* wproj = (float*)p;
    cudaGetSymbolAddress(&p, g_wfc1);  float* wfc1  = (float*)p;
    cudaGetSymbolAddress(&p, g_wfc2);  float* wfc2  = (float*)p;

    cudaFuncSetAttribute(attn_mma, cudaFuncAttributeMaxDynamicSharedMemorySize,
                         ATTN_SMEM);
    cudaFuncSetAttribute(gemm_tf32<0>, cudaFuncAttributeMaxDynamicSharedMemorySize,
                         GEMM_SMEM);
    cudaFuncSetAttribute(gemm_tf32<1>, cudaFuncAttributeMaxDynamicSharedMemorySize,
                         GEMM_SMEM);
    cudaFuncSetAttribute(gemm_tf32<2>, cudaFuncAttributeMaxDynamicSharedMemorySize,
                         GEMM_SMEM);

    // Pre-round weights to tf32 (RNA)
    cvt_tf32_kernel<<<(EMBED * QKV_C / 4 + 255) / 256, 256>>>(qkv_w, wqkv,
                                                              EMBED * QKV_C / 4);
    cvt_tf32_kernel<<<(EMBED * EMBED / 4 + 255) / 256, 256>>>(proj_w, wproj,
                                                              EMBED * EMBED / 4);
    cvt_tf32_kernel<<<(EMBED * HIDDEN / 4 + 255) / 256, 256>>>(fc1_w, wfc1,
                                                               EMBED * HIDDEN / 4);
    cvt_tf32_kernel<<<(HIDDEN * EMBED / 4 + 255) / 256, 256>>>(fc2_w, wfc2,
                                                               HIDDEN * EMBED / 4);

    // x1 = x + proj(attn(ln1(x)))
    ln_kernel<<<ROWS, 256>>>(x, ln1_w, ln1_b, xn);
    gemm_tf32<0><<<dim3(QKV_C / BN, ROWS / BM), 256, GEMM_SMEM>>>(
        xn, wqkv, qkv_b, nullptr, qkv, EMBED, QKV_C);
    attn_mma<<<dim3(SEQ / 64, BATCH * HEADS), 128, ATTN_SMEM>>>(qkv, att);
    gemm_tf32<2><<<dim3(EMBED / BN, ROWS / BM), 256, GEMM_SMEM>>>(
        att, wproj, proj_b, x, x1, EMBED, EMBED);

    // out = x1 + fc2(gelu(fc1(ln2(x1))))
    ln_kernel<<<ROWS, 256>>>(x1, ln2_w, ln2_b, xn);
    gemm_tf32<1><<<dim3(HIDDEN / BN, ROWS / BM), 256, GEMM_SMEM>>>(
        xn, wfc1, fc1_b, nullptr, h, EMBED, HIDDEN);
    gemm_tf32<2><<<dim3(EMBED / BN, ROWS / BM), 256, GEMM_SMEM>>>(
        h, wfc2, fc2_b, x1, out, HIDDEN, EMBED);
}

// round 7
// speedup vs baseline: 3.7990x; 1.0522x over previous
#include <cuda_runtime.h>
#include <math.h>
#include <stdint.h>

#define EMBED 1024
#define HEADS 16
#define HEAD_DIM 64
#define HIDDEN 4096
#define BATCH 2
#define SEQ 2048
#define ROWS (BATCH * SEQ)
#define QKV_C (3 * EMBED)

// ---- GEMM tiling ----
#define BM 128
#define BN 128
#define BK 32
#define STAGES 3
#define APITCH 36
#define BPITCH 136
#define ASTG (BM * APITCH)
#define BSTG (BK * BPITCH)
#define STG_F (ASTG + BSTG)
#define GEMM_SMEM (STG_F * STAGES * 4)  // 107520 B

// ---- Attention tiling ----
#define QROWS 128
#define QP 68
#define VP 72
#define KVSTG (64 * QP + 64 * VP)
#define ATTN_SMEM ((QROWS * QP + 2 * KVSTG) * 4)  // 106496 B

// Scratch (no cudaMalloc allowed)
__device__ float g_xn[(size_t)ROWS * EMBED];
__device__ float g_qkv[(size_t)ROWS * QKV_C];
__device__ float g_att[(size_t)ROWS * EMBED];
__device__ float g_x1[(size_t)ROWS * EMBED];
__device__ float g_h[(size_t)ROWS * HIDDEN];

// ---------------------------------------------------------------------------
__device__ __forceinline__ float f2tf32(float f) {
    uint32_t u;
    asm("cvt.rna.tf32.f32 %0, %1;" : "=r"(u) : "f"(f));
    return __uint_as_float(u);
}

__device__ __forceinline__ float gelu_exact(float x) {
    return 0.5f * x * (1.0f + erff(x * 0.70710678118654752f));
}

__device__ __forceinline__ void mma_tf32(float c[4], const uint32_t a[4],
                                         const uint32_t b[2]) {
    asm volatile(
        "mma.sync.aligned.m16n8k8.row.col.f32.tf32.tf32.f32 "
        "{%0,%1,%2,%3},{%4,%5,%6,%7},{%8,%9},{%0,%1,%2,%3};\n"
        : "+f"(c[0]), "+f"(c[1]), "+f"(c[2]), "+f"(c[3])
        : "r"(a[0]), "r"(a[1]), "r"(a[2]), "r"(a[3]), "r"(b[0]), "r"(b[1]));
}

__device__ __forceinline__ void cp16(uint32_t saddr, const void* gptr) {
    asm volatile("cp.async.cg.shared.global [%0], [%1], 16;\n" ::"r"(saddr),
                 "l"(gptr));
}

// ---------------------------------------------------------------------------
// LayerNorm (emits tf32 RNA-rounded output — consumed only as GEMM A operand)
// ---------------------------------------------------------------------------
__global__ __launch_bounds__(256) void ln_kernel(const float* __restrict__ x,
                                                 const float* __restrict__ w,
                                                 const float* __restrict__ b,
                                                 float* __restrict__ out) {
    int row = blockIdx.x;
    int t = threadIdx.x;
    const float4* xr = (const float4*)(x + (size_t)row * EMBED);
    float4 v = xr[t];
    float s = v.x + v.y + v.z + v.w;
    float q = v.x * v.x + v.y * v.y + v.z * v.z + v.w * v.w;
#pragma unroll
    for (int o = 16; o > 0; o >>= 1) {
        s += __shfl_xor_sync(0xffffffffu, s, o);
        q += __shfl_xor_sync(0xffffffffu, q, o);
    }
    __shared__ float rs[8], rq[8];
    if ((t & 31) == 0) { rs[t >> 5] = s; rq[t >> 5] = q; }
    __syncthreads();
    float ts = 0.f, tq = 0.f;
#pragma unroll
    for (int i = 0; i < 8; i++) { ts += rs[i]; tq += rq[i]; }
    float mu = ts * (1.0f / EMBED);
    float var = tq * (1.0f / EMBED) - mu * mu;
    float rstd = rsqrtf(var + 1e-5f);
    float4 wv = ((const float4*)w)[t];
    float4 bv = ((const float4*)b)[t];
    float4 o;
    o.x = f2tf32((v.x - mu) * rstd * wv.x + bv.x);
    o.y = f2tf32((v.y - mu) * rstd * wv.y + bv.y);
    o.z = f2tf32((v.z - mu) * rstd * wv.z + bv.z);
    o.w = f2tf32((v.w - mu) * rstd * wv.w + bv.w);
    ((float4*)(out + (size_t)row * EMBED))[t] = o;
}

// ---------------------------------------------------------------------------
// tf32 GEMM, cp.async 3-stage pipeline, BK=32, register-double-buffered frags.
// W is raw fp32 (hardware truncates to tf32). A is pre-RNA-rounded.
// EPI: 0 = bias + cvt, 1 = bias + GELU + cvt, 2 = bias + residual (fp32 out)
// ---------------------------------------------------------------------------
template <int EPI>
__global__ __launch_bounds__(256, 1) void gemm_tf32(const float* __restrict__ A,
                                                    const float* __restrict__ W,
                                                    const float* __restrict__ bias,
                                                    const float* __restrict__ res,
                                                    float* __restrict__ C,
                                                    int K, int Nc) {
    extern __shared__ float sm[];
    const uint32_t sb = (uint32_t)__cvta_generic_to_shared(sm);
    const int tid = threadIdx.x;
    const int warp = tid >> 5, lane = tid & 31;
    const int g = lane >> 2, t = lane & 3;
    const int wm = (warp >> 1) * 32, wn = (warp & 1) * 64;
    const int brow = blockIdx.y, bcol = blockIdx.x;

    const float* Aptr = A + (size_t)(brow * BM) * K;
    const float* Wptr = W + (size_t)bcol * BN;

    const int arow = tid >> 3;
    const int acol = (tid & 7) * 4;
    const int brw = tid >> 5;
    const int bcl = (tid & 31) * 4;

    float acc[2][8][4];
#pragma unroll
    for (int i = 0; i < 2; i++)
#pragma unroll
        for (int j = 0; j < 8; j++)
#pragma unroll
            for (int c = 0; c < 4; c++) acc[i][j][c] = 0.f;

    const int nch = K / BK;

    auto issue = [&](int kt) {
        const int s = kt % STAGES;
        const uint32_t Asm = sb + (uint32_t)(s * STG_F) * 4u;
        const uint32_t Bsm = Asm + ASTG * 4u;
#pragma unroll
        for (int i = 0; i < 4; i++) {
            const int r = arow + 32 * i;
            cp16(Asm + (uint32_t)(r * APITCH + acol) * 4u,
                 Aptr + (size_t)r * K + kt * BK + acol);
        }
#pragma unroll
        for (int i = 0; i < 4; i++) {
            const int r = brw + 8 * i;
            cp16(Bsm + (uint32_t)(r * BPITCH + bcl) * 4u,
                 Wptr + (size_t)(kt * BK + r) * Nc + bcl);
        }
    };

    issue(0);
    asm volatile("cp.async.commit_group;" ::: "memory");
    issue(1);
    asm volatile("cp.async.commit_group;" ::: "memory");

    for (int kt = 0; kt < nch; kt++) {
        asm volatile("cp.async.wait_group 1;" ::: "memory");
        __syncthreads();

        const int s = kt % STAGES;
        const float* As = sm + s * STG_F;
        const float* Bs = As + ASTG;

        uint32_t afr[2][2][4], bfr[2][8][2];
        auto ldfrag = [&](int ks, int buf) {
#pragma unroll
            for (int i = 0; i < 2; i++) {
                const float* Ab = As + (wm + i * 16 + g) * APITCH + ks * 8;
                afr[buf][i][0] = __float_as_uint(Ab[t]);
                afr[buf][i][1] = __float_as_uint(Ab[8 * APITCH + t]);
                afr[buf][i][2] = __float_as_uint(Ab[t + 4]);
                afr[buf][i][3] = __float_as_uint(Ab[8 * APITCH + t + 4]);
            }
            const float* Bb = Bs + (ks * 8 + t) * BPITCH + wn + g;
#pragma unroll
            for (int j = 0; j < 8; j++) {
                bfr[buf][j][0] = __float_as_uint(Bb[j * 8]);
                bfr[buf][j][1] = __float_as_uint(Bb[4 * BPITCH + j * 8]);
            }
        };

        ldfrag(0, 0);
#pragma unroll
        for (int ks = 0; ks < 4; ks++) {
            const int cur = ks & 1;
            if (ks < 3) ldfrag(ks + 1, cur ^ 1);
#pragma unroll
            for (int i = 0; i < 2; i++)
#pragma unroll
                for (int j = 0; j < 8; j++)
                    mma_tf32(acc[i][j], afr[cur][i], bfr[cur][j]);
        }

        if (kt + 2 < nch) issue(kt + 2);
        asm volatile("cp.async.commit_group;" ::: "memory");
    }

    // Epilogue
    const int colb = bcol * BN + wn;
#pragma unroll
    for (int i = 0; i < 2; i++) {
        const size_t r0 = (size_t)(brow * BM + wm + i * 16 + g);
        const size_t r1 = r0 + 8;
#pragma unroll
        for (int j = 0; j < 8; j++) {
            const int c0 = colb + j * 8 + 2 * t;
            float2 bv = *(const float2*)(bias + c0);
            float2 o0 = make_float2(acc[i][j][0] + bv.x, acc[i][j][1] + bv.y);
            float2 o1 = make_float2(acc[i][j][2] + bv.x, acc[i][j][3] + bv.y);
            if (EPI == 0) {
                o0.x = f2tf32(o0.x); o0.y = f2tf32(o0.y);
                o1.x = f2tf32(o1.x); o1.y = f2tf32(o1.y);
            } else if (EPI == 1) {
                o0.x = f2tf32(gelu_exact(o0.x)); o0.y = f2tf32(gelu_exact(o0.y));
                o1.x = f2tf32(gelu_exact(o1.x)); o1.y = f2tf32(gelu_exact(o1.y));
            } else {
                float2 r0v = *(const float2*)(res + r0 * Nc + c0);
                float2 r1v = *(const float2*)(res + r1 * Nc + c0);
                o0.x += r0v.x; o0.y += r0v.y;
                o1.x += r1v.x; o1.y += r1v.y;
            }
            *(float2*)(C + r0 * Nc + c0) = o0;
            *(float2*)(C + r1 * Nc + c0) = o1;
        }
    }
}

// ---------------------------------------------------------------------------
// Tensor-core flash attention (tf32), cp.async double-buffered K/V tiles.
// 8 warps, 128 q-rows/block (16 rows/warp), 64-key tiles.
// ---------------------------------------------------------------------------
__global__ __launch_bounds__(256) void attn_mma(const float* __restrict__ qkv,
                                                float* __restrict__ out) {
    extern __shared__ float sma[];
    float* Qs = sma;  // [128][QP]; per-warp 16-row sub-blocks double as P
    const uint32_t sb = (uint32_t)__cvta_generic_to_shared(sma);
    const uint32_t kvb = sb + QROWS * QP * 4;

    const int bh = blockIdx.y;
    const int b = bh >> 4, h = bh & 15;
    const int qblk = blockIdx.x;
    const int tid = threadIdx.x;
    const int w = tid >> 5, lane = tid & 31;
    const int g = lane >> 2, t = lane & 3;
    const int wm = w * 16;

    const float* qbase =
        qkv + (size_t)(b * SEQ + qblk * QROWS) * QKV_C + h * HEAD_DIM;
    const float* kbase = qkv + (size_t)(b * SEQ) * QKV_C + EMBED + h * HEAD_DIM;
    const float* vbase = qkv + (size_t)(b * SEQ) * QKV_C + 2 * EMBED + h * HEAD_DIM;

    // K/V tile loader: tile tt -> stage s (64 rows each)
    const int lr = tid >> 4;           // 0..15, +16*i
    const int lc = (tid & 15) * 4;
    auto issue_kv = [&](int tt, int s) {
        const uint32_t kd = kvb + (uint32_t)(s * KVSTG) * 4u;
        const uint32_t vd = kd + 64 * QP * 4u;
        const float* kp = kbase + (size_t)(tt * 64) * QKV_C;
        const float* vp = vbase + (size_t)(tt * 64) * QKV_C;
#pragma unroll
        for (int i = 0; i < 4; i++) {
            const int r = lr + 16 * i;
            cp16(kd + (uint32_t)(r * QP + lc) * 4u, kp + (size_t)r * QKV_C + lc);
            cp16(vd + (uint32_t)(r * VP + lc) * 4u, vp + (size_t)r * QKV_C + lc);
        }
    };

    issue_kv(0, 0);
    asm volatile("cp.async.commit_group;" ::: "memory");
    issue_kv(1, 1);
    asm volatile("cp.async.commit_group;" ::: "memory");

    // Load Q tile (128 rows) to smem, then into registers (pre-scaled 1/8)
    for (int it = tid; it < QROWS * 16; it += 256) {
        int r = it >> 4, c4 = (it & 15) * 4;
        *(float4*)(Qs + r * QP + c4) =
            *(const float4*)(qbase + (size_t)r * QKV_C + c4);
    }
    __syncthreads();

    uint32_t qa[8][4];
    float* Pw = Qs + wm * QP;  // warp-private 16-row region
#pragma unroll
    for (int kk = 0; kk < 8; kk++) {
        qa[kk][0] = __float_as_uint(0.125f * Pw[g * QP + kk * 8 + t]);
        qa[kk][1] = __float_as_uint(0.125f * Pw[(g + 8) * QP + kk * 8 + t]);
        qa[kk][2] = __float_as_uint(0.125f * Pw[g * QP + kk * 8 + t + 4]);
        qa[kk][3] = __float_as_uint(0.125f * Pw[(g + 8) * QP + kk * 8 + t + 4]);
    }

    float m0 = -INFINITY, m1 = -INFINITY, l0 = 0.f, l1 = 0.f;
    float o[8][4];
#pragma unroll
    for (int j = 0; j < 8; j++)
#pragma unroll
        for (int c = 0; c < 4; c++) o[j][c] = 0.f;

    const int ntiles = SEQ / 64;
    for (int it = 0; it < ntiles; it++) {
        asm volatile("cp.async.wait_group 1;" ::: "memory");
        __syncthreads();

        const int s = it & 1;
        const float* Ks = sma + QROWS * QP + s * KVSTG;
        const float* Vs = Ks + 64 * QP;

        // S = (Q*scale) @ K^T
        float sacc[8][4];
#pragma unroll
        for (int j = 0; j < 8; j++)
#pragma unroll
            for (int c = 0; c < 4; c++) sacc[j][c] = 0.f;
#pragma unroll
        for (int kk = 0; kk < 8; kk++) {
            uint32_t bf[8][2];
#pragma unroll
            for (int j = 0; j < 8; j++) {
                const float* Kb = Ks + (j * 8 + g) * QP + kk * 8 + t;
                bf[j][0] = __float_as_uint(Kb[0]);
                bf[j][1] = __float_as_uint(Kb[4]);
            }
#pragma unroll
            for (int j = 0; j < 8; j++) mma_tf32(sacc[j], qa[kk], bf[j]);
        }

        // Online softmax
        float mx0 = -INFINITY, mx1 = -INFINITY;
#pragma unroll
        for (int j = 0; j < 8; j++) {
            mx0 = fmaxf(mx0, fmaxf(sacc[j][0], sacc[j][1]));
            mx1 = fmaxf(mx1, fmaxf(sacc[j][2], sacc[j][3]));
        }
#pragma unroll
        for (int off = 1; off < 4; off <<= 1) {
            mx0 = fmaxf(mx0, __shfl_xor_sync(0xffffffffu, mx0, off));
            mx1 = fmaxf(mx1, __shfl_xor_sync(0xffffffffu, mx1, off));
        }
        float mn0 = fmaxf(m0, mx0), mn1 = fmaxf(m1, mx1);
        float a0 = __expf(m0 - mn0), a1 = __expf(m1 - mn1);
        float s0 = 0.f, s1 = 0.f;
#pragma unroll
        for (int j = 0; j < 8; j++) {
            float p0 = f2tf32(__expf(sacc[j][0] - mn0));
            float p1 = f2tf32(__expf(sacc[j][1] - mn0));
            float p2 = f2tf32(__expf(sacc[j][2] - mn1));
            float p3 = f2tf32(__expf(sacc[j][3] - mn1));
            s0 += p0 + p1; s1 += p2 + p3;
            *(float2*)(Pw + g * QP + j * 8 + 2 * t) = make_float2(p0, p1);
            *(float2*)(Pw + (g + 8) * QP + j * 8 + 2 * t) = make_float2(p2, p3);
        }
#pragma unroll
        for (int off = 1; off < 4; off <<= 1) {
            s0 += __shfl_xor_sync(0xffffffffu, s0, off);
            s1 += __shfl_xor_sync(0xffffffffu, s1, off);
        }
        l0 = l0 * a0 + s0; l1 = l1 * a1 + s1;
        m0 = mn0; m1 = mn1;
#pragma unroll
        for (int j = 0; j < 8; j++) {
            o[j][0] *= a0; o[j][1] *= a0; o[j][2] *= a1; o[j][3] *= a1;
        }
        __syncwarp();

        // O += P @ V
#pragma unroll
        for (int kk = 0; kk < 8; kk++) {
            uint32_t pa[4];
            pa[0] = __float_as_uint(Pw[g * QP + kk * 8 + t]);
            pa[1] = __float_as_uint(Pw[(g + 8) * QP + kk * 8 + t]);
            pa[2] = __float_as_uint(Pw[g * QP + kk * 8 + t + 4]);
            pa[3] = __float_as_uint(Pw[(g + 8) * QP + kk * 8 + t + 4]);
            uint32_t bf[8][2];
#pragma unroll
            for (int j = 0; j < 8; j++) {
                bf[j][0] = __float_as_uint(Vs[(kk * 8 + t) * VP + j * 8 + g]);
                bf[j][1] = __float_as_uint(Vs[(kk * 8 + t + 4) * VP + j * 8 + g]);
            }
#pragma unroll
            for (int j = 0; j < 8; j++) mma_tf32(o[j], pa, bf[j]);
        }

        __syncthreads();
        if (it + 2 < ntiles) issue_kv(it + 2, s);
        asm volatile("cp.async.commit_group;" ::: "memory");
    }

    // Epilogue: normalize, tf32-round (feeds proj GEMM A), store
    float inv0 = 1.f / l0, inv1 = 1.f / l1;
    const int row0 = qblk * QROWS + wm + g;
    float* ob = out + (size_t)(b * SEQ) * EMBED + h * HEAD_DIM;
#pragma unroll
    for (int j = 0; j < 8; j++) {
        float2 v0 = make_float2(f2tf32(o[j][0] * inv0), f2tf32(o[j][1] * inv0));
        float2 v1 = make_float2(f2tf32(o[j][2] * inv1), f2tf32(o[j][3] * inv1));
        *(float2*)(ob + (size_t)row0 * EMBED + j * 8 + 2 * t) = v0;
        *(float2*)(ob + (size_t)(row0 + 8) * EMBED + j * 8 + 2 * t) = v1;
    }
}

// ---------------------------------------------------------------------------
extern "C" void kernel_launch(void* const* d_in, const int* in_sizes, int n_in,
                              void* d_out, int out_size) {
    const float* x      = (const float*)d_in[0];
    const float* ln1_w  = (const float*)d_in[1];
    const float* ln1_b  = (const float*)d_in[2];
    const float* ln2_w  = (const float*)d_in[3];
    const float* ln2_b  = (const float*)d_in[4];
    const float* qkv_w  = (const float*)d_in[5];
    const float* qkv_b  = (const float*)d_in[6];
    const float* proj_w = (const float*)d_in[7];
    const float* proj_b = (const float*)d_in[8];
    const float* fc1_w  = (const float*)d_in[9];
    const float* fc1_b  = (const float*)d_in[10];
    const float* fc2_w  = (const float*)d_in[11];
    const float* fc2_b  = (const float*)d_in[12];
    float* out = (float*)d_out;

    void* p;
    cudaGetSymbolAddress(&p, g_xn);  float* xn  = (float*)p;
    cudaGetSymbolAddress(&p, g_qkv); float* qkv = (float*)p;
    cudaGetSymbolAddress(&p, g_att); float* att = (float*)p;
    cudaGetSymbolAddress(&p, g_x1);  float* x1  = (float*)p;
    cudaGetSymbolAddress(&p, g_h);   float* h   = (float*)p;

    cudaFuncSetAttribute(attn_mma, cudaFuncAttributeMaxDynamicSharedMemorySize,
                         ATTN_SMEM);
    cudaFuncSetAttribute(gemm_tf32<0>, cudaFuncAttributeMaxDynamicSharedMemorySize,
                         GEMM_SMEM);
    cudaFuncSetAttribute(gemm_tf32<1>, cudaFuncAttributeMaxDynamicSharedMemorySize,
                         GEMM_SMEM);
    cudaFuncSetAttribute(gemm_tf32<2>, cudaFuncAttributeMaxDynamicSharedMemorySize,
                         GEMM_SMEM);

    // x1 = x + proj(attn(ln1(x)))
    ln_kernel<<<ROWS, 256>>>(x, ln1_w, ln1_b, xn);
    gemm_tf32<0><<<dim3(QKV_C / BN, ROWS / BM), 256, GEMM_SMEM>>>(
        xn, qkv_w, qkv_b, nullptr, qkv, EMBED, QKV_C);
    attn_mma<<<dim3(SEQ / QROWS, BATCH * HEADS), 256, ATTN_SMEM>>>(qkv, att);
    gemm_tf32<2><<<dim3(EMBED / BN, ROWS / BM), 256, GEMM_SMEM>>>(
        att, proj_w, proj_b, x, x1, EMBED, EMBED);

    // out = x1 + fc2(gelu(fc1(ln2(x1))))
    ln_kernel<<<ROWS, 256>>>(x1, ln2_w, ln2_b, xn);
    gemm_tf32<1><<<dim3(HIDDEN / BN, ROWS / BM), 256, GEMM_SMEM>>>(
        xn, fc1_w, fc1_b, nullptr, h, EMBED, HIDDEN);
    gemm_tf32<2><<<dim3(EMBED / BN, ROWS / BM), 256, GEMM_SMEM>>>(
        h, fc2_w, fc2_b, x1, out, HIDDEN, EMBED);
}

// round 9
// speedup vs baseline: 4.1729x; 1.0984x over previous
#include <cuda_runtime.h>
#include <math.h>
#include <stdint.h>

#define EMBED 1024
#define HEADS 16
#define HEAD_DIM 64
#define HIDDEN 4096
#define BATCH 2
#define SEQ 2048
#define ROWS (BATCH * SEQ)
#define QKV_C (3 * EMBED)

// ---- GEMM tiling ----
#define BM 128
#define BN 128
#define BK 32
#define STAGES 3
#define APITCH 36
#define BPITCH 136
#define ASTG (BM * APITCH)
#define BSTG (BK * BPITCH)
#define STG_F (ASTG + BSTG)
#define GEMM_SMEM (STG_F * STAGES * 4)  // 107520 B

// ---- Attention tiling ----
#define QROWS 128
#define QP 68
#define VP 72
#define KVSTG (64 * QP + 64 * VP)
#define ATTN_SMEM ((QROWS * QP + 2 * KVSTG) * 4)  // 106496 B

// Scratch (no cudaMalloc allowed)
__device__ float g_xn[(size_t)ROWS * EMBED];
__device__ float g_qkv[(size_t)ROWS * QKV_C];
__device__ float g_att[(size_t)ROWS * EMBED];
__device__ float g_x1[(size_t)ROWS * EMBED];
__device__ float g_h[(size_t)ROWS * HIDDEN];

// ---------------------------------------------------------------------------
__device__ __forceinline__ float f2tf32(float f) {
    uint32_t u;
    asm("cvt.rna.tf32.f32 %0, %1;" : "=r"(u) : "f"(f));
    return __uint_as_float(u);
}

__device__ __forceinline__ float gelu_exact(float x) {
    return 0.5f * x * (1.0f + erff(x * 0.70710678118654752f));
}

__device__ __forceinline__ void mma_tf32(float c[4], const uint32_t a[4],
                                         const uint32_t b[2]) {
    asm volatile(
        "mma.sync.aligned.m16n8k8.row.col.f32.tf32.tf32.f32 "
        "{%0,%1,%2,%3},{%4,%5,%6,%7},{%8,%9},{%0,%1,%2,%3};\n"
        : "+f"(c[0]), "+f"(c[1]), "+f"(c[2]), "+f"(c[3])
        : "r"(a[0]), "r"(a[1]), "r"(a[2]), "r"(a[3]), "r"(b[0]), "r"(b[1]));
}

__device__ __forceinline__ void cp16(uint32_t saddr, const void* gptr) {
    asm volatile("cp.async.cg.shared.global [%0], [%1], 16;\n" ::"r"(saddr),
                 "l"(gptr));
}

// ---------------------------------------------------------------------------
// LayerNorm (emits tf32 RNA-rounded output — consumed only as GEMM A operand)
// ---------------------------------------------------------------------------
__global__ __launch_bounds__(256) void ln_kernel(const float* __restrict__ x,
                                                 const float* __restrict__ w,
                                                 const float* __restrict__ b,
                                                 float* __restrict__ out) {
    int row = blockIdx.x;
    int t = threadIdx.x;
    const float4* xr = (const float4*)(x + (size_t)row * EMBED);
    float4 v = xr[t];
    float s = v.x + v.y + v.z + v.w;
    float q = v.x * v.x + v.y * v.y + v.z * v.z + v.w * v.w;
#pragma unroll
    for (int o = 16; o > 0; o >>= 1) {
        s += __shfl_xor_sync(0xffffffffu, s, o);
        q += __shfl_xor_sync(0xffffffffu, q, o);
    }
    __shared__ float rs[8], rq[8];
    if ((t & 31) == 0) { rs[t >> 5] = s; rq[t >> 5] = q; }
    __syncthreads();
    float ts = 0.f, tq = 0.f;
#pragma unroll
    for (int i = 0; i < 8; i++) { ts += rs[i]; tq += rq[i]; }
    float mu = ts * (1.0f / EMBED);
    float var = tq * (1.0f / EMBED) - mu * mu;
    float rstd = rsqrtf(var + 1e-5f);
    float4 wv = ((const float4*)w)[t];
    float4 bv = ((const float4*)b)[t];
    float4 o;
    o.x = f2tf32((v.x - mu) * rstd * wv.x + bv.x);
    o.y = f2tf32((v.y - mu) * rstd * wv.y + bv.y);
    o.z = f2tf32((v.z - mu) * rstd * wv.z + bv.z);
    o.w = f2tf32((v.w - mu) * rstd * wv.w + bv.w);
    ((float4*)(out + (size_t)row * EMBED))[t] = o;
}

// ---------------------------------------------------------------------------
// tf32 GEMM: 128 threads, 4 warps of 64x64, 3-stage cp.async, 2 CTAs/SM.
// W is raw fp32 (hardware truncates to tf32). A is pre-RNA-rounded.
// EPI: 0 = bias + cvt, 1 = bias + GELU + cvt, 2 = bias + residual (fp32 out)
// ---------------------------------------------------------------------------
template <int EPI>
__global__ __launch_bounds__(128, 2) void gemm_tf32(const float* __restrict__ A,
                                                    const float* __restrict__ W,
                                                    const float* __restrict__ bias,
                                                    const float* __restrict__ res,
                                                    float* __restrict__ C,
                                                    int K, int Nc) {
    extern __shared__ float sm[];
    const uint32_t sb = (uint32_t)__cvta_generic_to_shared(sm);
    const int tid = threadIdx.x;
    const int warp = tid >> 5, lane = tid & 31;
    const int g = lane >> 2, t = lane & 3;
    const int wm = (warp >> 1) * 64, wn = (warp & 1) * 64;
    const int brow = blockIdx.y, bcol = blockIdx.x;

    const float* Aptr = A + (size_t)(brow * BM) * K;
    const float* Wptr = W + (size_t)bcol * BN;

    // A: 128 rows x 32 cols, 8 threads/row -> 16 rows/pass, 8 passes
    const int arow = tid >> 3;
    const int acol = (tid & 7) * 4;
    // B: 32 rows x 128 cols, 32 threads/row -> 4 rows/pass, 8 passes
    const int brw = tid >> 5;
    const int bcl = (tid & 31) * 4;

    float acc[4][8][4];
#pragma unroll
    for (int i = 0; i < 4; i++)
#pragma unroll
        for (int j = 0; j < 8; j++)
#pragma unroll
            for (int c = 0; c < 4; c++) acc[i][j][c] = 0.f;

    const int nch = K / BK;

    auto issue = [&](int kt) {
        const int s = kt % STAGES;
        const uint32_t Asm = sb + (uint32_t)(s * STG_F) * 4u;
        const uint32_t Bsm = Asm + ASTG * 4u;
#pragma unroll
        for (int i = 0; i < 8; i++) {
            const int r = arow + 16 * i;
            cp16(Asm + (uint32_t)(r * APITCH + acol) * 4u,
                 Aptr + (size_t)r * K + kt * BK + acol);
        }
#pragma unroll
        for (int i = 0; i < 8; i++) {
            const int r = brw + 4 * i;
            cp16(Bsm + (uint32_t)(r * BPITCH + bcl) * 4u,
                 Wptr + (size_t)(kt * BK + r) * Nc + bcl);
        }
    };

    issue(0);
    asm volatile("cp.async.commit_group;" ::: "memory");
    issue(1);
    asm volatile("cp.async.commit_group;" ::: "memory");

    for (int kt = 0; kt < nch; kt++) {
        asm volatile("cp.async.wait_group 1;" ::: "memory");
        __syncthreads();

        const int s = kt % STAGES;
        const float* As = sm + s * STG_F;
        const float* Bs = As + ASTG;

#pragma unroll
        for (int ks = 0; ks < 4; ks++) {
            uint32_t bfr[8][2];
            const float* Bb = Bs + (ks * 8 + t) * BPITCH + wn + g;
#pragma unroll
            for (int j = 0; j < 8; j++) {
                bfr[j][0] = __float_as_uint(Bb[j * 8]);
                bfr[j][1] = __float_as_uint(Bb[4 * BPITCH + j * 8]);
            }
#pragma unroll
            for (int i = 0; i < 4; i++) {
                uint32_t afr[4];
                const float* Ab = As + (wm + i * 16 + g) * APITCH + ks * 8;
                afr[0] = __float_as_uint(Ab[t]);
                afr[1] = __float_as_uint(Ab[8 * APITCH + t]);
                afr[2] = __float_as_uint(Ab[t + 4]);
                afr[3] = __float_as_uint(Ab[8 * APITCH + t + 4]);
#pragma unroll
                for (int j = 0; j < 8; j++) mma_tf32(acc[i][j], afr, bfr[j]);
            }
        }

        if (kt + 2 < nch) issue(kt + 2);
        asm volatile("cp.async.commit_group;" ::: "memory");
    }

    // Epilogue
    const int colb = bcol * BN + wn;
#pragma unroll
    for (int i = 0; i < 4; i++) {
        const size_t r0 = (size_t)(brow * BM + wm + i * 16 + g);
        const size_t r1 = r0 + 8;
#pragma unroll
        for (int j = 0; j < 8; j++) {
            const int c0 = colb + j * 8 + 2 * t;
            float2 bv = *(const float2*)(bias + c0);
            float2 o0 = make_float2(acc[i][j][0] + bv.x, acc[i][j][1] + bv.y);
            float2 o1 = make_float2(acc[i][j][2] + bv.x, acc[i][j][3] + bv.y);
            if (EPI == 0) {
                o0.x = f2tf32(o0.x); o0.y = f2tf32(o0.y);
                o1.x = f2tf32(o1.x); o1.y = f2tf32(o1.y);
            } else if (EPI == 1) {
                o0.x = f2tf32(gelu_exact(o0.x)); o0.y = f2tf32(gelu_exact(o0.y));
                o1.x = f2tf32(gelu_exact(o1.x)); o1.y = f2tf32(gelu_exact(o1.y));
            } else {
                float2 r0v = *(const float2*)(res + r0 * Nc + c0);
                float2 r1v = *(const float2*)(res + r1 * Nc + c0);
                o0.x += r0v.x; o0.y += r0v.y;
                o1.x += r1v.x; o1.y += r1v.y;
            }
            *(float2*)(C + r0 * Nc + c0) = o0;
            *(float2*)(C + r1 * Nc + c0) = o1;
        }
    }
}

// ---------------------------------------------------------------------------
// Tensor-core flash attention (tf32), cp.async double-buffered K/V tiles.
// 8 warps, 128 q-rows/block (16 rows/warp), 64-key tiles.
// ---------------------------------------------------------------------------
__global__ __launch_bounds__(256) void attn_mma(const float* __restrict__ qkv,
                                                float* __restrict__ out) {
    extern __shared__ float sma[];
    float* Qs = sma;  // [128][QP]; per-warp 16-row sub-blocks double as P
    const uint32_t sb = (uint32_t)__cvta_generic_to_shared(sma);
    const uint32_t kvb = sb + QROWS * QP * 4;

    const int bh = blockIdx.y;
    const int b = bh >> 4, h = bh & 15;
    const int qblk = blockIdx.x;
    const int tid = threadIdx.x;
    const int w = tid >> 5, lane = tid & 31;
    const int g = lane >> 2, t = lane & 3;
    const int wm = w * 16;

    const float* qbase =
        qkv + (size_t)(b * SEQ + qblk * QROWS) * QKV_C + h * HEAD_DIM;
    const float* kbase = qkv + (size_t)(b * SEQ) * QKV_C + EMBED + h * HEAD_DIM;
    const float* vbase = qkv + (size_t)(b * SEQ) * QKV_C + 2 * EMBED + h * HEAD_DIM;

    const int lr = tid >> 4;
    const int lc = (tid & 15) * 4;
    auto issue_kv = [&](int tt, int s) {
        const uint32_t kd = kvb + (uint32_t)(s * KVSTG) * 4u;
        const uint32_t vd = kd + 64 * QP * 4u;
        const float* kp = kbase + (size_t)(tt * 64) * QKV_C;
        const float* vp = vbase + (size_t)(tt * 64) * QKV_C;
#pragma unroll
        for (int i = 0; i < 4; i++) {
            const int r = lr + 16 * i;
            cp16(kd + (uint32_t)(r * QP + lc) * 4u, kp + (size_t)r * QKV_C + lc);
            cp16(vd + (uint32_t)(r * VP + lc) * 4u, vp + (size_t)r * QKV_C + lc);
        }
    };

    issue_kv(0, 0);
    asm volatile("cp.async.commit_group;" ::: "memory");
    issue_kv(1, 1);
    asm volatile("cp.async.commit_group;" ::: "memory");

    for (int it = tid; it < QROWS * 16; it += 256) {
        int r = it >> 4, c4 = (it & 15) * 4;
        *(float4*)(Qs + r * QP + c4) =
            *(const float4*)(qbase + (size_t)r * QKV_C + c4);
    }
    __syncthreads();

    uint32_t qa[8][4];
    float* Pw = Qs + wm * QP;
#pragma unroll
    for (int kk = 0; kk < 8; kk++) {
        qa[kk][0] = __float_as_uint(0.125f * Pw[g * QP + kk * 8 + t]);
        qa[kk][1] = __float_as_uint(0.125f * Pw[(g + 8) * QP + kk * 8 + t]);
        qa[kk][2] = __float_as_uint(0.125f * Pw[g * QP + kk * 8 + t + 4]);
        qa[kk][3] = __float_as_uint(0.125f * Pw[(g + 8) * QP + kk * 8 + t + 4]);
    }

    float m0 = -INFINITY, m1 = -INFINITY, l0 = 0.f, l1 = 0.f;
    float o[8][4];
#pragma unroll
    for (int j = 0; j < 8; j++)
#pragma unroll
        for (int c = 0; c < 4; c++) o[j][c] = 0.f;

    const int ntiles = SEQ / 64;
    for (int it = 0; it < ntiles; it++) {
        asm volatile("cp.async.wait_group 1;" ::: "memory");
        __syncthreads();

        const int s = it & 1;
        const float* Ks = sma + QROWS * QP + s * KVSTG;
        const float* Vs = Ks + 64 * QP;

        float sacc[8][4];
#pragma unroll
        for (int j = 0; j < 8; j++)
#pragma unroll
            for (int c = 0; c < 4; c++) sacc[j][c] = 0.f;
#pragma unroll
        for (int kk = 0; kk < 8; kk++) {
            uint32_t bf[8][2];
#pragma unroll
            for (int j = 0; j < 8; j++) {
                const float* Kb = Ks + (j * 8 + g) * QP + kk * 8 + t;
                bf[j][0] = __float_as_uint(Kb[0]);
                bf[j][1] = __float_as_uint(Kb[4]);
            }
#pragma unroll
            for (int j = 0; j < 8; j++) mma_tf32(sacc[j], qa[kk], bf[j]);
        }

        float mx0 = -INFINITY, mx1 = -INFINITY;
#pragma unroll
        for (int j = 0; j < 8; j++) {
            mx0 = fmaxf(mx0, fmaxf(sacc[j][0], sacc[j][1]));
            mx1 = fmaxf(mx1, fmaxf(sacc[j][2], sacc[j][3]));
        }
#pragma unroll
        for (int off = 1; off < 4; off <<= 1) {
            mx0 = fmaxf(mx0, __shfl_xor_sync(0xffffffffu, mx0, off));
            mx1 = fmaxf(mx1, __shfl_xor_sync(0xffffffffu, mx1, off));
        }
        float mn0 = fmaxf(m0, mx0), mn1 = fmaxf(m1, mx1);
        float a0 = __expf(m0 - mn0), a1 = __expf(m1 - mn1);
        float s0 = 0.f, s1 = 0.f;
#pragma unroll
        for (int j = 0; j < 8; j++) {
            float p0 = f2tf32(__expf(sacc[j][0] - mn0));
            float p1 = f2tf32(__expf(sacc[j][1] - mn0));
            float p2 = f2tf32(__expf(sacc[j][2] - mn1));
            float p3 = f2tf32(__expf(sacc[j][3] - mn1));
            s0 += p0 + p1; s1 += p2 + p3;
            *(float2*)(Pw + g * QP + j * 8 + 2 * t) = make_float2(p0, p1);
            *(float2*)(Pw + (g + 8) * QP + j * 8 + 2 * t) = make_float2(p2, p3);
        }
#pragma unroll
        for (int off = 1; off < 4; off <<= 1) {
            s0 += __shfl_xor_sync(0xffffffffu, s0, off);
            s1 += __shfl_xor_sync(0xffffffffu, s1, off);
        }
        l0 = l0 * a0 + s0; l1 = l1 * a1 + s1;
        m0 = mn0; m1 = mn1;
#pragma unroll
        for (int j = 0; j < 8; j++) {
            o[j][0] *= a0; o[j][1] *= a0; o[j][2] *= a1; o[j][3] *= a1;
        }
        __syncwarp();

#pragma unroll
        for (int kk = 0; kk < 8; kk++) {
            uint32_t pa[4];
            pa[0] = __float_as_uint(Pw[g * QP + kk * 8 + t]);
            pa[1] = __float_as_uint(Pw[(g + 8) * QP + kk * 8 + t]);
            pa[2] = __float_as_uint(Pw[g * QP + kk * 8 + t + 4]);
            pa[3] = __float_as_uint(Pw[(g + 8) * QP + kk * 8 + t + 4]);
            uint32_t bf[8][2];
#pragma unroll
            for (int j = 0; j < 8; j++) {
                bf[j][0] = __float_as_uint(Vs[(kk * 8 + t) * VP + j * 8 + g]);
                bf[j][1] = __float_as_uint(Vs[(kk * 8 + t + 4) * VP + j * 8 + g]);
            }
#pragma unroll
            for (int j = 0; j < 8; j++) mma_tf32(o[j], pa, bf[j]);
        }

        __syncthreads();
        if (it + 2 < ntiles) issue_kv(it + 2, s);
        asm volatile("cp.async.commit_group;" ::: "memory");
    }

    float inv0 = 1.f / l0, inv1 = 1.f / l1;
    const int row0 = qblk * QROWS + wm + g;
    float* ob = out + (size_t)(b * SEQ) * EMBED + h * HEAD_DIM;
#pragma unroll
    for (int j = 0; j < 8; j++) {
        float2 v0 = make_float2(f2tf32(o[j][0] * inv0), f2tf32(o[j][1] * inv0));
        float2 v1 = make_float2(f2tf32(o[j][2] * inv1), f2tf32(o[j][3] * inv1));
        *(float2*)(ob + (size_t)row0 * EMBED + j * 8 + 2 * t) = v0;
        *(float2*)(ob + (size_t)(row0 + 8) * EMBED + j * 8 + 2 * t) = v1;
    }
}

// ---------------------------------------------------------------------------
extern "C" void kernel_launch(void* const* d_in, const int* in_sizes, int n_in,
                              void* d_out, int out_size) {
    const float* x      = (const float*)d_in[0];
    const float* ln1_w  = (const float*)d_in[1];
    const float* ln1_b  = (const float*)d_in[2];
    const float* ln2_w  = (const float*)d_in[3];
    const float* ln2_b  = (const float*)d_in[4];
    const float* qkv_w  = (const float*)d_in[5];
    const float* qkv_b  = (const float*)d_in[6];
    const float* proj_w = (const float*)d_in[7];
    const float* proj_b = (const float*)d_in[8];
    const float* fc1_w  = (const float*)d_in[9];
    const float* fc1_b  = (const float*)d_in[10];
    const float* fc2_w  = (const float*)d_in[11];
    const float* fc2_b  = (const float*)d_in[12];
    float* out = (float*)d_out;

    void* p;
    cudaGetSymbolAddress(&p, g_xn);  float* xn  = (float*)p;
    cudaGetSymbolAddress(&p, g_qkv); float* qkv = (float*)p;
    cudaGetSymbolAddress(&p, g_att); float* att = (float*)p;
    cudaGetSymbolAddress(&p, g_x1);  float* x1  = (float*)p;
    cudaGetSymbolAddress(&p, g_h);   float* h   = (float*)p;

    cudaFuncSetAttribute(attn_mma, cudaFuncAttributeMaxDynamicSharedMemorySize,
                         ATTN_SMEM);
    cudaFuncSetAttribute(gemm_tf32<0>, cudaFuncAttributeMaxDynamicSharedMemorySize,
                         GEMM_SMEM);
    cudaFuncSetAttribute(gemm_tf32<1>, cudaFuncAttributeMaxDynamicSharedMemorySize,
                         GEMM_SMEM);
    cudaFuncSetAttribute(gemm_tf32<2>, cudaFuncAttributeMaxDynamicSharedMemorySize,
                         GEMM_SMEM);

    // x1 = x + proj(attn(ln1(x)))
    ln_kernel<<<ROWS, 256>>>(x, ln1_w, ln1_b, xn);
    gemm_tf32<0><<<dim3(QKV_C / BN, ROWS / BM), 128, GEMM_SMEM>>>(
        xn, qkv_w, qkv_b, nullptr, qkv, EMBED, QKV_C);
    attn_mma<<<dim3(SEQ / QROWS, BATCH * HEADS), 256, ATTN_SMEM>>>(qkv, att);
    gemm_tf32<2><<<dim3(EMBED / BN, ROWS / BM), 128, GEMM_SMEM>>>(
        att, proj_w, proj_b, x, x1, EMBED, EMBED);

    // out = x1 + fc2(gelu(fc1(ln2(x1))))
    ln_kernel<<<ROWS, 256>>>(x1, ln2_w, ln2_b, xn);
    gemm_tf32<1><<<dim3(HIDDEN / BN, ROWS / BM), 128, GEMM_SMEM>>>(
        xn, fc1_w, fc1_b, nullptr, h, EMBED, HIDDEN);
    gemm_tf32<2><<<dim3(EMBED / BN, ROWS / BM), 128, GEMM_SMEM>>>(
        h, fc2_w, fc2_b, x1, out, HIDDEN, EMBED);
}

// round 11
// speedup vs baseline: 4.3026x; 1.0311x over previous
#include <cuda_runtime.h>
#include <math.h>
#include <stdint.h>

#define EMBED 1024
#define HEADS 16
#define HEAD_DIM 64
#define HIDDEN 4096
#define BATCH 2
#define SEQ 2048
#define ROWS (BATCH * SEQ)
#define QKV_C (3 * EMBED)

// ---- GEMM tiling ----
#define BM 128
#define BN 128
#define BK 32
#define STAGES 3
#define APITCH 36    // 144B rows: 16B-aligned, ldmatrix bank-quads distinct
#define BPITCH 136
#define ASTG (BM * APITCH)
#define BSTG (BK * BPITCH)
#define STG_F (ASTG + BSTG)
#define GEMM_SMEM (STG_F * STAGES * 4)  // 107520 B

// ---- Attention tiling ----
#define QROWS 128
#define QP 68   // 272B rows: 16B-aligned
#define VP 72
#define KVSTG (64 * QP + 64 * VP)
#define ATTN_SMEM ((QROWS * QP + 2 * KVSTG) * 4)  // 106496 B

// Scratch (no cudaMalloc allowed)
__device__ float g_xn[(size_t)ROWS * EMBED];
__device__ float g_qkv[(size_t)ROWS * QKV_C];
__device__ float g_att[(size_t)ROWS * EMBED];
__device__ float g_x1[(size_t)ROWS * EMBED];
__device__ float g_h[(size_t)ROWS * HIDDEN];

// ---------------------------------------------------------------------------
__device__ __forceinline__ float f2tf32(float f) {
    uint32_t u;
    asm("cvt.rna.tf32.f32 %0, %1;" : "=r"(u) : "f"(f));
    return __uint_as_float(u);
}

__device__ __forceinline__ float gelu_exact(float x) {
    return 0.5f * x * (1.0f + erff(x * 0.70710678118654752f));
}

__device__ __forceinline__ void mma_tf32(float c[4], const uint32_t a[4],
                                         const uint32_t b[2]) {
    asm volatile(
        "mma.sync.aligned.m16n8k8.row.col.f32.tf32.tf32.f32 "
        "{%0,%1,%2,%3},{%4,%5,%6,%7},{%8,%9},{%0,%1,%2,%3};\n"
        : "+f"(c[0]), "+f"(c[1]), "+f"(c[2]), "+f"(c[3])
        : "r"(a[0]), "r"(a[1]), "r"(a[2]), "r"(a[3]), "r"(b[0]), "r"(b[1]));
}

__device__ __forceinline__ void cp16(uint32_t saddr, const void* gptr) {
    asm volatile("cp.async.cg.shared.global [%0], [%1], 16;\n" ::"r"(saddr),
                 "l"(gptr));
}

// ldmatrix x4: each lane passes the shared-space address of one 16B row chunk.
__device__ __forceinline__ void ldsm4(uint32_t r[4], uint32_t saddr) {
    asm volatile(
        "ldmatrix.sync.aligned.m8n8.x4.shared.b16 {%0,%1,%2,%3}, [%4];\n"
        : "=r"(r[0]), "=r"(r[1]), "=r"(r[2]), "=r"(r[3])
        : "r"(saddr));
}

// ---------------------------------------------------------------------------
// LayerNorm (emits tf32 RNA-rounded output — consumed only as GEMM A operand)
// ---------------------------------------------------------------------------
__global__ __launch_bounds__(256) void ln_kernel(const float* __restrict__ x,
                                                 const float* __restrict__ w,
                                                 const float* __restrict__ b,
                                                 float* __restrict__ out) {
    int row = blockIdx.x;
    int t = threadIdx.x;
    const float4* xr = (const float4*)(x + (size_t)row * EMBED);
    float4 v = xr[t];
    float s = v.x + v.y + v.z + v.w;
    float q = v.x * v.x + v.y * v.y + v.z * v.z + v.w * v.w;
#pragma unroll
    for (int o = 16; o > 0; o >>= 1) {
        s += __shfl_xor_sync(0xffffffffu, s, o);
        q += __shfl_xor_sync(0xffffffffu, q, o);
    }
    __shared__ float rs[8], rq[8];
    if ((t & 31) == 0) { rs[t >> 5] = s; rq[t >> 5] = q; }
    __syncthreads();
    float ts = 0.f, tq = 0.f;
#pragma unroll
    for (int i = 0; i < 8; i++) { ts += rs[i]; tq += rq[i]; }
    float mu = ts * (1.0f / EMBED);
    float var = tq * (1.0f / EMBED) - mu * mu;
    float rstd = rsqrtf(var + 1e-5f);
    float4 wv = ((const float4*)w)[t];
    float4 bv = ((const float4*)b)[t];
    float4 o;
    o.x = f2tf32((v.x - mu) * rstd * wv.x + bv.x);
    o.y = f2tf32((v.y - mu) * rstd * wv.y + bv.y);
    o.z = f2tf32((v.z - mu) * rstd * wv.z + bv.z);
    o.w = f2tf32((v.w - mu) * rstd * wv.w + bv.w);
    ((float4*)(out + (size_t)row * EMBED))[t] = o;
}

// ---------------------------------------------------------------------------
// tf32 GEMM: 128 threads, 4 warps of 64x64, 3-stage cp.async, ldmatrix A-frags.
// W is raw fp32 (hardware truncates to tf32). A is pre-RNA-rounded.
// EPI: 0 = bias + cvt, 1 = bias + GELU + cvt, 2 = bias + residual (fp32 out)
// ---------------------------------------------------------------------------
template <int EPI>
__global__ __launch_bounds__(128, 2) void gemm_tf32(const float* __restrict__ A,
                                                    const float* __restrict__ W,
                                                    const float* __restrict__ bias,
                                                    const float* __restrict__ res,
                                                    float* __restrict__ C,
                                                    int K, int Nc) {
    extern __shared__ float sm[];
    const uint32_t sb = (uint32_t)__cvta_generic_to_shared(sm);
    const int tid = threadIdx.x;
    const int warp = tid >> 5, lane = tid & 31;
    const int g = lane >> 2, t = lane & 3;
    const int wm = (warp >> 1) * 64, wn = (warp & 1) * 64;
    const int brow = blockIdx.y, bcol = blockIdx.x;

    const float* Aptr = A + (size_t)(brow * BM) * K;
    const float* Wptr = W + (size_t)bcol * BN;

    const int arow = tid >> 3;
    const int acol = (tid & 7) * 4;
    const int brw = tid >> 5;
    const int bcl = (tid & 31) * 4;

    // ldmatrix lane-address offset within the A tile (bytes):
    // row (lane&15), halfword-chunk (lane>>4)
    const uint32_t a_lds_off =
        (uint32_t)((lane & 15) * APITCH * 4 + (lane >> 4) * 16);

    float acc[4][8][4];
#pragma unroll
    for (int i = 0; i < 4; i++)
#pragma unroll
        for (int j = 0; j < 8; j++)
#pragma unroll
            for (int c = 0; c < 4; c++) acc[i][j][c] = 0.f;

    const int nch = K / BK;

    auto issue = [&](int kt) {
        const int s = kt % STAGES;
        const uint32_t Asm = sb + (uint32_t)(s * STG_F) * 4u;
        const uint32_t Bsm = Asm + ASTG * 4u;
#pragma unroll
        for (int i = 0; i < 8; i++) {
            const int r = arow + 16 * i;
            cp16(Asm + (uint32_t)(r * APITCH + acol) * 4u,
                 Aptr + (size_t)r * K + kt * BK + acol);
        }
#pragma unroll
        for (int i = 0; i < 8; i++) {
            const int r = brw + 4 * i;
            cp16(Bsm + (uint32_t)(r * BPITCH + bcl) * 4u,
                 Wptr + (size_t)(kt * BK + r) * Nc + bcl);
        }
    };

    issue(0);
    asm volatile("cp.async.commit_group;" ::: "memory");
    issue(1);
    asm volatile("cp.async.commit_group;" ::: "memory");

    for (int kt = 0; kt < nch; kt++) {
        asm volatile("cp.async.wait_group 1;" ::: "memory");
        __syncthreads();

        const int s = kt % STAGES;
        const float* Bs = sm + s * STG_F + ASTG;
        const uint32_t Astage = sb + (uint32_t)(s * STG_F) * 4u;

#pragma unroll
        for (int ks = 0; ks < 4; ks++) {
            uint32_t bfr[8][2];
            const float* Bb = Bs + (ks * 8 + t) * BPITCH + wn + g;
#pragma unroll
            for (int j = 0; j < 8; j++) {
                bfr[j][0] = __float_as_uint(Bb[j * 8]);
                bfr[j][1] = __float_as_uint(Bb[4 * BPITCH + j * 8]);
            }
#pragma unroll
            for (int i = 0; i < 4; i++) {
                uint32_t afr[4];
                ldsm4(afr, Astage + (uint32_t)((wm + i * 16) * APITCH * 4) +
                               a_lds_off + (uint32_t)(ks * 32));
#pragma unroll
                for (int j = 0; j < 8; j++) mma_tf32(acc[i][j], afr, bfr[j]);
            }
        }

        if (kt + 2 < nch) issue(kt + 2);
        asm volatile("cp.async.commit_group;" ::: "memory");
    }

    // Epilogue
    const int colb = bcol * BN + wn;
#pragma unroll
    for (int i = 0; i < 4; i++) {
        const size_t r0 = (size_t)(brow * BM + wm + i * 16 + g);
        const size_t r1 = r0 + 8;
#pragma unroll
        for (int j = 0; j < 8; j++) {
            const int c0 = colb + j * 8 + 2 * t;
            float2 bv = *(const float2*)(bias + c0);
            float2 o0 = make_float2(acc[i][j][0] + bv.x, acc[i][j][1] + bv.y);
            float2 o1 = make_float2(acc[i][j][2] + bv.x, acc[i][j][3] + bv.y);
            if (EPI == 0) {
                o0.x = f2tf32(o0.x); o0.y = f2tf32(o0.y);
                o1.x = f2tf32(o1.x); o1.y = f2tf32(o1.y);
            } else if (EPI == 1) {
                o0.x = f2tf32(gelu_exact(o0.x)); o0.y = f2tf32(gelu_exact(o0.y));
                o1.x = f2tf32(gelu_exact(o1.x)); o1.y = f2tf32(gelu_exact(o1.y));
            } else {
                float2 r0v = *(const float2*)(res + r0 * Nc + c0);
                float2 r1v = *(const float2*)(res + r1 * Nc + c0);
                o0.x += r0v.x; o0.y += r0v.y;
                o1.x += r1v.x; o1.y += r1v.y;
            }
            *(float2*)(C + r0 * Nc + c0) = o0;
            *(float2*)(C + r1 * Nc + c0) = o1;
        }
    }
}

// ---------------------------------------------------------------------------
// Tensor-core flash attention (tf32), cp.async double-buffered K/V tiles,
// ldmatrix for K-fragments and P-fragments.
// 8 warps, 128 q-rows/block (16 rows/warp), 64-key tiles.
// ---------------------------------------------------------------------------
__global__ __launch_bounds__(256) void attn_mma(const float* __restrict__ qkv,
                                                float* __restrict__ out) {
    extern __shared__ float sma[];
    float* Qs = sma;  // [128][QP]; per-warp 16-row sub-blocks double as P
    const uint32_t sb = (uint32_t)__cvta_generic_to_shared(sma);
    const uint32_t kvb = sb + QROWS * QP * 4;

    const int bh = blockIdx.y;
    const int b = bh >> 4, h = bh & 15;
    const int qblk = blockIdx.x;
    const int tid = threadIdx.x;
    const int w = tid >> 5, lane = tid & 31;
    const int g = lane >> 2, t = lane & 3;
    const int wm = w * 16;

    const float* qbase =
        qkv + (size_t)(b * SEQ + qblk * QROWS) * QKV_C + h * HEAD_DIM;
    const float* kbase = qkv + (size_t)(b * SEQ) * QKV_C + EMBED + h * HEAD_DIM;
    const float* vbase = qkv + (size_t)(b * SEQ) * QKV_C + 2 * EMBED + h * HEAD_DIM;

    const int lr = tid >> 4;
    const int lc = (tid & 15) * 4;
    auto issue_kv = [&](int tt, int s) {
        const uint32_t kd = kvb + (uint32_t)(s * KVSTG) * 4u;
        const uint32_t vd = kd + 64 * QP * 4u;
        const float* kp = kbase + (size_t)(tt * 64) * QKV_C;
        const float* vp = vbase + (size_t)(tt * 64) * QKV_C;
#pragma unroll
        for (int i = 0; i < 4; i++) {
            const int r = lr + 16 * i;
            cp16(kd + (uint32_t)(r * QP + lc) * 4u, kp + (size_t)r * QKV_C + lc);
            cp16(vd + (uint32_t)(r * VP + lc) * 4u, vp + (size_t)r * QKV_C + lc);
        }
    };

    issue_kv(0, 0);
    asm volatile("cp.async.commit_group;" ::: "memory");
    issue_kv(1, 1);
    asm volatile("cp.async.commit_group;" ::: "memory");

    for (int it = tid; it < QROWS * 16; it += 256) {
        int r = it >> 4, c4 = (it & 15) * 4;
        *(float4*)(Qs + r * QP + c4) =
            *(const float4*)(qbase + (size_t)r * QKV_C + c4);
    }
    __syncthreads();

    uint32_t qa[8][4];
    float* Pw = Qs + wm * QP;
#pragma unroll
    for (int kk = 0; kk < 8; kk++) {
        qa[kk][0] = __float_as_uint(0.125f * Pw[g * QP + kk * 8 + t]);
        qa[kk][1] = __float_as_uint(0.125f * Pw[(g + 8) * QP + kk * 8 + t]);
        qa[kk][2] = __float_as_uint(0.125f * Pw[g * QP + kk * 8 + t + 4]);
        qa[kk][3] = __float_as_uint(0.125f * Pw[(g + 8) * QP + kk * 8 + t + 4]);
    }

    // ldmatrix lane offsets (bytes within a 64xQP K tile / 16xQP P tile):
    // K: matrix m=lane>>3 -> j=2jj+(lane>>4), half=(lane>>3)&1, row=lane&7
    const uint32_t k_lds_off =
        (uint32_t)(((lane >> 4) * 8 + (lane & 7)) * QP * 4 +
                   ((lane >> 3) & 1) * 16);
    // P (A-style): row=lane&15, half=lane>>4
    const uint32_t p_lds_off =
        (uint32_t)((lane & 15) * QP * 4 + (lane >> 4) * 16);
    const uint32_t pw_base = sb + (uint32_t)(wm * QP * 4);

    float m0 = -INFINITY, m1 = -INFINITY, l0 = 0.f, l1 = 0.f;
    float o[8][4];
#pragma unroll
    for (int j = 0; j < 8; j++)
#pragma unroll
        for (int c = 0; c < 4; c++) o[j][c] = 0.f;

    const int ntiles = SEQ / 64;
    for (int it = 0; it < ntiles; it++) {
        asm volatile("cp.async.wait_group 1;" ::: "memory");
        __syncthreads();

        const int s = it & 1;
        const uint32_t Kbase = kvb + (uint32_t)(s * KVSTG) * 4u;
        const float* Vs = sma + QROWS * QP + s * KVSTG + 64 * QP;

        // S = (Q*scale) @ K^T  — K frags via ldmatrix (2 j per x4)
        float sacc[8][4];
#pragma unroll
        for (int j = 0; j < 8; j++)
#pragma unroll
            for (int c = 0; c < 4; c++) sacc[j][c] = 0.f;
#pragma unroll
        for (int kk = 0; kk < 8; kk++) {
            uint32_t kf[16];
#pragma unroll
            for (int jj = 0; jj < 4; jj++) {
                ldsm4(kf + jj * 4, Kbase + (uint32_t)(jj * 16 * QP * 4) +
                                       k_lds_off + (uint32_t)(kk * 32));
            }
#pragma unroll
            for (int j = 0; j < 8; j++) {
                mma_tf32(sacc[j], qa[kk], kf + (j >> 1) * 4 + (j & 1) * 2);
            }
        }

        // Online softmax
        float mx0 = -INFINITY, mx1 = -INFINITY;
#pragma unroll
        for (int j = 0; j < 8; j++) {
            mx0 = fmaxf(mx0, fmaxf(sacc[j][0], sacc[j][1]));
            mx1 = fmaxf(mx1, fmaxf(sacc[j][2], sacc[j][3]));
        }
#pragma unroll
        for (int off = 1; off < 4; off <<= 1) {
            mx0 = fmaxf(mx0, __shfl_xor_sync(0xffffffffu, mx0, off));
            mx1 = fmaxf(mx1, __shfl_xor_sync(0xffffffffu, mx1, off));
        }
        float mn0 = fmaxf(m0, mx0), mn1 = fmaxf(m1, mx1);
        float a0 = __expf(m0 - mn0), a1 = __expf(m1 - mn1);
        float s0 = 0.f, s1 = 0.f;
#pragma unroll
        for (int j = 0; j < 8; j++) {
            float p0 = f2tf32(__expf(sacc[j][0] - mn0));
            float p1 = f2tf32(__expf(sacc[j][1] - mn0));
            float p2 = f2tf32(__expf(sacc[j][2] - mn1));
            float p3 = f2tf32(__expf(sacc[j][3] - mn1));
            s0 += p0 + p1; s1 += p2 + p3;
            *(float2*)(Pw + g * QP + j * 8 + 2 * t) = make_float2(p0, p1);
            *(float2*)(Pw + (g + 8) * QP + j * 8 + 2 * t) = make_float2(p2, p3);
        }
#pragma unroll
        for (int off = 1; off < 4; off <<= 1) {
            s0 += __shfl_xor_sync(0xffffffffu, s0, off);
            s1 += __shfl_xor_sync(0xffffffffu, s1, off);
        }
        l0 = l0 * a0 + s0; l1 = l1 * a1 + s1;
        m0 = mn0; m1 = mn1;
#pragma unroll
        for (int j = 0; j < 8; j++) {
            o[j][0] *= a0; o[j][1] *= a0; o[j][2] *= a1; o[j][3] *= a1;
        }
        __syncwarp();

        // O += P @ V  — P frags via ldmatrix
#pragma unroll
        for (int kk = 0; kk < 8; kk++) {
            uint32_t pa[4];
            ldsm4(pa, pw_base + p_lds_off + (uint32_t)(kk * 32));
            uint32_t bf[8][2];
#pragma unroll
            for (int j = 0; j < 8; j++) {
                bf[j][0] = __float_as_uint(Vs[(kk * 8 + t) * VP + j * 8 + g]);
                bf[j][1] = __float_as_uint(Vs[(kk * 8 + t + 4) * VP + j * 8 + g]);
            }
#pragma unroll
            for (int j = 0; j < 8; j++) mma_tf32(o[j], pa, bf[j]);
        }

        __syncthreads();
        if (it + 2 < ntiles) issue_kv(it + 2, s);
        asm volatile("cp.async.commit_group;" ::: "memory");
    }

    float inv0 = 1.f / l0, inv1 = 1.f / l1;
    const int row0 = qblk * QROWS + wm + g;
    float* ob = out + (size_t)(b * SEQ) * EMBED + h * HEAD_DIM;
#pragma unroll
    for (int j = 0; j < 8; j++) {
        float2 v0 = make_float2(f2tf32(o[j][0] * inv0), f2tf32(o[j][1] * inv0));
        float2 v1 = make_float2(f2tf32(o[j][2] * inv1), f2tf32(o[j][3] * inv1));
        *(float2*)(ob + (size_t)row0 * EMBED + j * 8 + 2 * t) = v0;
        *(float2*)(ob + (size_t)(row0 + 8) * EMBED + j * 8 + 2 * t) = v1;
    }
}

// ---------------------------------------------------------------------------
extern "C" void kernel_launch(void* const* d_in, const int* in_sizes, int n_in,
                              void* d_out, int out_size) {
    const float* x      = (const float*)d_in[0];
    const float* ln1_w  = (const float*)d_in[1];
    const float* ln1_b  = (const float*)d_in[2];
    const float* ln2_w  = (const float*)d_in[3];
    const float* ln2_b  = (const float*)d_in[4];
    const float* qkv_w  = (const float*)d_in[5];
    const float* qkv_b  = (const float*)d_in[6];
    const float* proj_w = (const float*)d_in[7];
    const float* proj_b = (const float*)d_in[8];
    const float* fc1_w  = (const float*)d_in[9];
    const float* fc1_b  = (const float*)d_in[10];
    const float* fc2_w  = (const float*)d_in[11];
    const float* fc2_b  = (const float*)d_in[12];
    float* out = (float*)d_out;

    void* p;
    cudaGetSymbolAddress(&p, g_xn);  float* xn  = (float*)p;
    cudaGetSymbolAddress(&p, g_qkv); float* qkv = (float*)p;
    cudaGetSymbolAddress(&p, g_att); float* att = (float*)p;
    cudaGetSymbolAddress(&p, g_x1);  float* x1  = (float*)p;
    cudaGetSymbolAddress(&p, g_h);   float* h   = (float*)p;

    cudaFuncSetAttribute(attn_mma, cudaFuncAttributeMaxDynamicSharedMemorySize,
                         ATTN_SMEM);
    cudaFuncSetAttribute(gemm_tf32<0>, cudaFuncAttributeMaxDynamicSharedMemorySize,
                         GEMM_SMEM);
    cudaFuncSetAttribute(gemm_tf32<1>, cudaFuncAttributeMaxDynamicSharedMemorySize,
                         GEMM_SMEM);
    cudaFuncSetAttribute(gemm_tf32<2>, cudaFuncAttributeMaxDynamicSharedMemorySize,
                         GEMM_SMEM);

    // x1 = x + proj(attn(ln1(x)))
    ln_kernel<<<ROWS, 256>>>(x, ln1_w, ln1_b, xn);
    gemm_tf32<0><<<dim3(QKV_C / BN, ROWS / BM), 128, GEMM_SMEM>>>(
        xn, qkv_w, qkv_b, nullptr, qkv, EMBED, QKV_C);
    attn_mma<<<dim3(SEQ / QROWS, BATCH * HEADS), 256, ATTN_SMEM>>>(qkv, att);
    gemm_tf32<2><<<dim3(EMBED / BN, ROWS / BM), 128, GEMM_SMEM>>>(
        att, proj_w, proj_b, x, x1, EMBED, EMBED);

    // out = x1 + fc2(gelu(fc1(ln2(x1))))
    ln_kernel<<<ROWS, 256>>>(x1, ln2_w, ln2_b, xn);
    gemm_tf32<1><<<dim3(HIDDEN / BN, ROWS / BM), 128, GEMM_SMEM>>>(
        xn, fc1_w, fc1_b, nullptr, h, EMBED, HIDDEN);
    gemm_tf32<2><<<dim3(EMBED / BN, ROWS / BM), 128, GEMM_SMEM>>>(
        h, fc2_w, fc2_b, x1, out, HIDDEN, EMBED);
}

// round 14
// speedup vs baseline: 7.5535x; 1.7556x over previous
#include <cuda_runtime.h>
#include <cuda_fp16.h>
#include <math.h>
#include <stdint.h>

#define EMBED 1024
#define HEADS 16
#define HEAD_DIM 64
#define HIDDEN 4096
#define BATCH 2
#define SEQ 2048
#define ROWS (BATCH * SEQ)
#define QKV_C (3 * EMBED)

// ---- GEMM tiling (fp16 operands) ----
#define BM 128
#define BN 128
#define BKH 64        // K halves per chunk
#define STAGES 3
#define APH 72        // A pitch (halves): 144B rows, conflict-free quads
#define BPH 136       // B pitch (halves): 272B rows, conflict-free quads
#define ASTGH (BM * APH)          // 9216 halves
#define BSTGH (BKH * BPH)         // 8704 halves
#define STGH (ASTGH + BSTGH)      // 17920 halves / stage
#define GEMM_SMEM (STGH * STAGES * 2)  // 107520 B

// ---- Attention tiling (fp16) ----
#define QROWS 128
#define QPH 72        // pitch for Q/K/V/P (halves)
#define KVSTGH (128 * QPH)        // K tile + V tile halves per stage
#define ATTN_SMEM ((QROWS * QPH + 2 * KVSTGH) * 2)  // 55296 B

// Scratch (no cudaMalloc allowed)
__device__ __half g_xn[(size_t)ROWS * EMBED];
__device__ __half g_qkv[(size_t)ROWS * QKV_C];
__device__ __half g_att[(size_t)ROWS * EMBED];
__device__ float  g_x1[(size_t)ROWS * EMBED];
__device__ __half g_h[(size_t)ROWS * HIDDEN];
__device__ __half g_wqkv[(size_t)EMBED * QKV_C];
__device__ __half g_wproj[(size_t)EMBED * EMBED];
__device__ __half g_wfc1[(size_t)EMBED * HIDDEN];
__device__ __half g_wfc2[(size_t)HIDDEN * EMBED];

// ---------------------------------------------------------------------------
__device__ __forceinline__ float gelu_exact(float x) {
    return 0.5f * x * (1.0f + erff(x * 0.70710678118654752f));
}

__device__ __forceinline__ void mma_fp16(float c[4], const uint32_t a[4],
                                         const uint32_t b[2]) {
    asm volatile(
        "mma.sync.aligned.m16n8k16.row.col.f32.f16.f16.f32 "
        "{%0,%1,%2,%3},{%4,%5,%6,%7},{%8,%9},{%0,%1,%2,%3};\n"
        : "+f"(c[0]), "+f"(c[1]), "+f"(c[2]), "+f"(c[3])
        : "r"(a[0]), "r"(a[1]), "r"(a[2]), "r"(a[3]), "r"(b[0]), "r"(b[1]));
}

__device__ __forceinline__ void cp16(uint32_t saddr, const void* gptr) {
    asm volatile("cp.async.cg.shared.global [%0], [%1], 16;\n" ::"r"(saddr),
                 "l"(gptr));
}

__device__ __forceinline__ void ldsm4(uint32_t r[4], uint32_t saddr) {
    asm volatile(
        "ldmatrix.sync.aligned.m8n8.x4.shared.b16 {%0,%1,%2,%3}, [%4];\n"
        : "=r"(r[0]), "=r"(r[1]), "=r"(r[2]), "=r"(r[3])
        : "r"(saddr));
}

__device__ __forceinline__ void ldsm4t(uint32_t r[4], uint32_t saddr) {
    asm volatile(
        "ldmatrix.sync.aligned.m8n8.x4.trans.shared.b16 {%0,%1,%2,%3}, [%4];\n"
        : "=r"(r[0]), "=r"(r[1]), "=r"(r[2]), "=r"(r[3])
        : "r"(saddr));
}

// ---------------------------------------------------------------------------
// Weight fp32 -> fp16 conversion (once per launch)
// ---------------------------------------------------------------------------
__global__ __launch_bounds__(256) void cvt_h_kernel(const float* __restrict__ in,
                                                    __half* __restrict__ out,
                                                    int n4) {
    int i = blockIdx.x * blockDim.x + threadIdx.x;
    if (i < n4) {
        float4 v = ((const float4*)in)[i];
        __half2 h0 = __floats2half2_rn(v.x, v.y);
        __half2 h1 = __floats2half2_rn(v.z, v.w);
        uint2 u;
        u.x = *(uint32_t*)&h0;
        u.y = *(uint32_t*)&h1;
        *(uint2*)(out + 4 * (size_t)i) = u;
    }
}

// ---------------------------------------------------------------------------
// LayerNorm -> fp16 output (consumed only as GEMM A operand)
// ---------------------------------------------------------------------------
__global__ __launch_bounds__(256) void ln_kernel(const float* __restrict__ x,
                                                 const float* __restrict__ w,
                                                 const float* __restrict__ b,
                                                 __half* __restrict__ out) {
    int row = blockIdx.x;
    int t = threadIdx.x;
    const float4* xr = (const float4*)(x + (size_t)row * EMBED);
    float4 v = xr[t];
    float s = v.x + v.y + v.z + v.w;
    float q = v.x * v.x + v.y * v.y + v.z * v.z + v.w * v.w;
#pragma unroll
    for (int o = 16; o > 0; o >>= 1) {
        s += __shfl_xor_sync(0xffffffffu, s, o);
        q += __shfl_xor_sync(0xffffffffu, q, o);
    }
    __shared__ float rs[8], rq[8];
    if ((t & 31) == 0) { rs[t >> 5] = s; rq[t >> 5] = q; }
    __syncthreads();
    float ts = 0.f, tq = 0.f;
#pragma unroll
    for (int i = 0; i < 8; i++) { ts += rs[i]; tq += rq[i]; }
    float mu = ts * (1.0f / EMBED);
    float var = tq * (1.0f / EMBED) - mu * mu;
    float rstd = rsqrtf(var + 1e-5f);
    float4 wv = ((const float4*)w)[t];
    float4 bv = ((const float4*)b)[t];
    float o0 = (v.x - mu) * rstd * wv.x + bv.x;
    float o1 = (v.y - mu) * rstd * wv.y + bv.y;
    float o2 = (v.z - mu) * rstd * wv.z + bv.z;
    float o3 = (v.w - mu) * rstd * wv.w + bv.w;
    __half2 h0 = __floats2half2_rn(o0, o1);
    __half2 h1 = __floats2half2_rn(o2, o3);
    uint2 u;
    u.x = *(uint32_t*)&h0;
    u.y = *(uint32_t*)&h1;
    *(uint2*)(out + (size_t)row * EMBED + t * 4) = u;
}

// ---------------------------------------------------------------------------
// fp16 GEMM: 128 threads, 4 warps of 64x64, BKH=64, 3-stage cp.async.
// EPI: 0 = bias -> half, 1 = bias + GELU -> half, 2 = bias + residual -> fp32
// ---------------------------------------------------------------------------
template <int EPI>
__global__ __launch_bounds__(128, 2) void gemm_fp16(
    const __half* __restrict__ A, const __half* __restrict__ W,
    const float* __restrict__ bias, const float* __restrict__ res,
    float* __restrict__ C, __half* __restrict__ Ch, int K, int Nc) {
    extern __shared__ __half smh[];
    const uint32_t sb = (uint32_t)__cvta_generic_to_shared(smh);
    const int tid = threadIdx.x;
    const int warp = tid >> 5, lane = tid & 31;
    const int g = lane >> 2, t = lane & 3;
    const int wm = (warp >> 1) * 64, wn = (warp & 1) * 64;
    const int brow = blockIdx.y, bcol = blockIdx.x;

    const __half* Aptr = A + (size_t)(brow * BM) * K;
    const __half* Wptr = W + (size_t)bcol * BN;

    // loaders: A 128x64 halves (8 chunks/row), B 64x128 halves (16 chunks/row)
    const int ar0 = tid >> 3;          // 0..15, +16*i
    const int ac = tid & 7;            // 16B chunk
    const int br0 = tid >> 4;          // 0..7, +8*i
    const int bc = tid & 15;

    // ldmatrix lane offsets (bytes)
    const uint32_t a_off =
        (uint32_t)(((lane & 7) + 8 * ((lane >> 3) & 1)) * APH * 2 +
                   (lane >> 4) * 16);
    const uint32_t b_off =
        (uint32_t)(((lane & 7) + 8 * ((lane >> 3) & 1)) * BPH * 2 +
                   (lane >> 4) * 16);

    float acc[4][8][4];
#pragma unroll
    for (int i = 0; i < 4; i++)
#pragma unroll
        for (int j = 0; j < 8; j++)
#pragma unroll
            for (int c = 0; c < 4; c++) acc[i][j][c] = 0.f;

    const int nch = K / BKH;

    auto issue = [&](int kt) {
        const int s = kt % STAGES;
        const uint32_t Asm = sb + (uint32_t)(s * STGH) * 2u;
        const uint32_t Bsm = Asm + ASTGH * 2u;
#pragma unroll
        for (int i = 0; i < 8; i++) {
            const int r = ar0 + 16 * i;
            cp16(Asm + (uint32_t)(r * APH + ac * 8) * 2u,
                 Aptr + (size_t)r * K + kt * BKH + ac * 8);
        }
#pragma unroll
        for (int i = 0; i < 8; i++) {
            const int r = br0 + 8 * i;
            cp16(Bsm + (uint32_t)(r * BPH + bc * 8) * 2u,
                 Wptr + (size_t)(kt * BKH + r) * Nc + bc * 8);
        }
    };

    issue(0);
    asm volatile("cp.async.commit_group;" ::: "memory");
    issue(1);
    asm volatile("cp.async.commit_group;" ::: "memory");

    for (int kt = 0; kt < nch; kt++) {
        asm volatile("cp.async.wait_group 1;" ::: "memory");
        __syncthreads();

        const int s = kt % STAGES;
        const uint32_t Astage = sb + (uint32_t)(s * STGH) * 2u;
        const uint32_t Bstage = Astage + ASTGH * 2u;

#pragma unroll
        for (int ks = 0; ks < 4; ks++) {
            uint32_t bfr[8][2];
#pragma unroll
            for (int jj = 0; jj < 4; jj++) {
                uint32_t r4[4];
                ldsm4t(r4, Bstage + (uint32_t)(ks * 16 * BPH * 2) +
                               (uint32_t)((wn + jj * 16) * 2) + b_off);
                bfr[2 * jj][0] = r4[0];
                bfr[2 * jj][1] = r4[1];
                bfr[2 * jj + 1][0] = r4[2];
                bfr[2 * jj + 1][1] = r4[3];
            }
#pragma unroll
            for (int i = 0; i < 4; i++) {
                uint32_t afr[4];
                ldsm4(afr, Astage + (uint32_t)((wm + i * 16) * APH * 2) +
                               (uint32_t)(ks * 32) + a_off);
#pragma unroll
                for (int j = 0; j < 8; j++) mma_fp16(acc[i][j], afr, bfr[j]);
            }
        }

        if (kt + 2 < nch) issue(kt + 2);
        asm volatile("cp.async.commit_group;" ::: "memory");
    }

    // Epilogue
    const int colb = bcol * BN + wn;
#pragma unroll
    for (int i = 0; i < 4; i++) {
        const size_t r0 = (size_t)(brow * BM + wm + i * 16 + g);
        const size_t r1 = r0 + 8;
#pragma unroll
        for (int j = 0; j < 8; j++) {
            const int c0 = colb + j * 8 + 2 * t;
            float2 bv = *(const float2*)(bias + c0);
            float o0x = acc[i][j][0] + bv.x, o0y = acc[i][j][1] + bv.y;
            float o1x = acc[i][j][2] + bv.x, o1y = acc[i][j][3] + bv.y;
            if (EPI == 0) {
                *(__half2*)(Ch + r0 * Nc + c0) = __floats2half2_rn(o0x, o0y);
                *(__half2*)(Ch + r1 * Nc + c0) = __floats2half2_rn(o1x, o1y);
            } else if (EPI == 1) {
                *(__half2*)(Ch + r0 * Nc + c0) =
                    __floats2half2_rn(gelu_exact(o0x), gelu_exact(o0y));
                *(__half2*)(Ch + r1 * Nc + c0) =
                    __floats2half2_rn(gelu_exact(o1x), gelu_exact(o1y));
            } else {
                float2 r0v = *(const float2*)(res + r0 * Nc + c0);
                float2 r1v = *(const float2*)(res + r1 * Nc + c0);
                *(float2*)(C + r0 * Nc + c0) =
                    make_float2(o0x + r0v.x, o0y + r0v.y);
                *(float2*)(C + r1 * Nc + c0) =
                    make_float2(o1x + r1v.x, o1y + r1v.y);
            }
        }
    }
}

// ---------------------------------------------------------------------------
// fp16 flash attention: 8 warps, 128 q-rows/CTA, 64-key tiles, cp.async
// double-buffered K/V, ldmatrix fragments everywhere. Output fp16.
// ---------------------------------------------------------------------------
__global__ __launch_bounds__(256) void attn_mma(const __half* __restrict__ qkv,
                                                __half* __restrict__ out) {
    extern __shared__ __half sma[];
    __half* Qs = sma;  // [128][QPH]; warp's 16-row block doubles as P
    const uint32_t sb = (uint32_t)__cvta_generic_to_shared(sma);
    const uint32_t kvb = sb + (uint32_t)(QROWS * QPH * 2);

    const int bh = blockIdx.y;
    const int b = bh >> 4, h = bh & 15;
    const int qblk = blockIdx.x;
    const int tid = threadIdx.x;
    const int w = tid >> 5, lane = tid & 31;
    const int g = lane >> 2, t = lane & 3;
    const int wm = w * 16;

    const __half* qbase =
        qkv + (size_t)(b * SEQ + qblk * QROWS) * QKV_C + h * HEAD_DIM;
    const __half* kbase = qkv + (size_t)(b * SEQ) * QKV_C + EMBED + h * HEAD_DIM;
    const __half* vbase =
        qkv + (size_t)(b * SEQ) * QKV_C + 2 * EMBED + h * HEAD_DIM;

    // K/V tile loader: 64 rows x 8 chunks each; 256 threads, 2 passes
    auto issue_kv = [&](int tt, int s) {
        const uint32_t kd = kvb + (uint32_t)(s * KVSTGH) * 2u;
        const uint32_t vd = kd + (uint32_t)(64 * QPH * 2);
        const __half* kp = kbase + (size_t)(tt * 64) * QKV_C;
        const __half* vp = vbase + (size_t)(tt * 64) * QKV_C;
#pragma unroll
        for (int i = 0; i < 2; i++) {
            const int idx = tid + 256 * i;
            const int r = idx >> 3, c = idx & 7;
            cp16(kd + (uint32_t)(r * QPH + c * 8) * 2u,
                 kp + (size_t)r * QKV_C + c * 8);
            cp16(vd + (uint32_t)(r * QPH + c * 8) * 2u,
                 vp + (size_t)r * QKV_C + c * 8);
        }
    };

    issue_kv(0, 0);
    asm volatile("cp.async.commit_group;" ::: "memory");
    issue_kv(1, 1);
    asm volatile("cp.async.commit_group;" ::: "memory");

    // Stage Q (pre-scaled by 1/8, exact in fp16)
    {
        const __half2 sc = __floats2half2_rn(0.125f, 0.125f);
        for (int idx = tid; idx < QROWS * 32; idx += 256) {
            int r = idx >> 5, c2 = idx & 31;
            __half2 v = *(const __half2*)(qbase + (size_t)r * QKV_C + c2 * 2);
            *(__half2*)(Qs + r * QPH + c2 * 2) = __hmul2(v, sc);
        }
    }
    __syncthreads();

    // ldmatrix lane offsets (bytes)
    const uint32_t a_off =
        (uint32_t)(((lane & 7) + 8 * ((lane >> 3) & 1)) * QPH * 2 +
                   (lane >> 4) * 16);
    const uint32_t k_off =
        (uint32_t)(((lane & 7) + 8 * (lane >> 4)) * QPH * 2 +
                   ((lane >> 3) & 1) * 16);
    const uint32_t v_off = a_off;  // same pattern (rows + dim-chunk select)
    const uint32_t pqbase = sb + (uint32_t)(wm * QPH * 2);

    // Q fragments (warp's own 16 rows)
    uint32_t qa[4][4];
#pragma unroll
    for (int kk = 0; kk < 4; kk++) ldsm4(qa[kk], pqbase + kk * 32 + a_off);

    __half* Pw = Qs + wm * QPH;

    float m0 = -INFINITY, m1 = -INFINITY, l0 = 0.f, l1 = 0.f;
    float o[8][4];
#pragma unroll
    for (int j = 0; j < 8; j++)
#pragma unroll
        for (int c = 0; c < 4; c++) o[j][c] = 0.f;

    const int ntiles = SEQ / 64;
    for (int it = 0; it < ntiles; it++) {
        asm volatile("cp.async.wait_group 1;" ::: "memory");
        __syncthreads();

        const int s = it & 1;
        const uint32_t Kbase = kvb + (uint32_t)(s * KVSTGH) * 2u;
        const uint32_t Vbase = Kbase + (uint32_t)(64 * QPH * 2);

        // S = (Q/8) @ K^T
        float sacc[8][4];
#pragma unroll
        for (int j = 0; j < 8; j++)
#pragma unroll
            for (int c = 0; c < 4; c++) sacc[j][c] = 0.f;
#pragma unroll
        for (int kk = 0; kk < 4; kk++) {
            uint32_t kfr[8][2];
#pragma unroll
            for (int jj = 0; jj < 4; jj++) {
                uint32_t r4[4];
                ldsm4(r4, Kbase + (uint32_t)(jj * 16 * QPH * 2) + kk * 32 + k_off);
                kfr[2 * jj][0] = r4[0];
                kfr[2 * jj][1] = r4[1];
                kfr[2 * jj + 1][0] = r4[2];
                kfr[2 * jj + 1][1] = r4[3];
            }
#pragma unroll
            for (int j = 0; j < 8; j++) mma_fp16(sacc[j], qa[kk], kfr[j]);
        }

        // Online softmax (rows g, g+8; reduce over quad lanes)
        float mx0 = -INFINITY, mx1 = -INFINITY;
#pragma unroll
        for (int j = 0; j < 8; j++) {
            mx0 = fmaxf(mx0, fmaxf(sacc[j][0], sacc[j][1]));
            mx1 = fmaxf(mx1, fmaxf(sacc[j][2], sacc[j][3]));
        }
#pragma unroll
        for (int off = 1; off < 4; off <<= 1) {
            mx0 = fmaxf(mx0, __shfl_xor_sync(0xffffffffu, mx0, off));
            mx1 = fmaxf(mx1, __shfl_xor_sync(0xffffffffu, mx1, off));
        }
        float mn0 = fmaxf(m0, mx0), mn1 = fmaxf(m1, mx1);
        float a0 = __expf(m0 - mn0), a1 = __expf(m1 - mn1);
        float s0 = 0.f, s1 = 0.f;
#pragma unroll
        for (int j = 0; j < 8; j++) {
            float p0 = __expf(sacc[j][0] - mn0);
            float p1 = __expf(sacc[j][1] - mn0);
            float p2 = __expf(sacc[j][2] - mn1);
            float p3 = __expf(sacc[j][3] - mn1);
            s0 += p0 + p1;
            s1 += p2 + p3;
            *(__half2*)(Pw + g * QPH + j * 8 + 2 * t) = __floats2half2_rn(p0, p1);
            *(__half2*)(Pw + (g + 8) * QPH + j * 8 + 2 * t) =
                __floats2half2_rn(p2, p3);
        }
#pragma unroll
        for (int off = 1; off < 4; off <<= 1) {
            s0 += __shfl_xor_sync(0xffffffffu, s0, off);
            s1 += __shfl_xor_sync(0xffffffffu, s1, off);
        }
        l0 = l0 * a0 + s0;
        l1 = l1 * a1 + s1;
        m0 = mn0;
        m1 = mn1;
#pragma unroll
        for (int j = 0; j < 8; j++) {
            o[j][0] *= a0; o[j][1] *= a0; o[j][2] *= a1; o[j][3] *= a1;
        }
        __syncwarp();

        // O += P @ V
#pragma unroll
        for (int kk = 0; kk < 4; kk++) {
            uint32_t pa[4];
            ldsm4(pa, pqbase + kk * 32 + a_off);
            uint32_t vfr[8][2];
#pragma unroll
            for (int jj = 0; jj < 4; jj++) {
                uint32_t r4[4];
                ldsm4t(r4,
                       Vbase + (uint32_t)(kk * 16 * QPH * 2) + jj * 32 + v_off);
                vfr[2 * jj][0] = r4[0];
                vfr[2 * jj][1] = r4[1];
                vfr[2 * jj + 1][0] = r4[2];
                vfr[2 * jj + 1][1] = r4[3];
            }
#pragma unroll
            for (int j = 0; j < 8; j++) mma_fp16(o[j], pa, vfr[j]);
        }

        __syncthreads();
        if (it + 2 < ntiles) issue_kv(it + 2, s);
        asm volatile("cp.async.commit_group;" ::: "memory");
    }

    // Epilogue: normalize -> fp16 (feeds proj GEMM A)
    float inv0 = 1.f / l0, inv1 = 1.f / l1;
    const int row0 = qblk * QROWS + wm + g;
    __half* ob = out + (size_t)(b * SEQ) * EMBED + h * HEAD_DIM;
#pragma unroll
    for (int j = 0; j < 8; j++) {
        *(__half2*)(ob + (size_t)row0 * EMBED + j * 8 + 2 * t) =
            __floats2half2_rn(o[j][0] * inv0, o[j][1] * inv0);
        *(__half2*)(ob + (size_t)(row0 + 8) * EMBED + j * 8 + 2 * t) =
            __floats2half2_rn(o[j][2] * inv1, o[j][3] * inv1);
    }
}

// ---------------------------------------------------------------------------
extern "C" void kernel_launch(void* const* d_in, const int* in_sizes, int n_in,
                              void* d_out, int out_size) {
    const float* x      = (const float*)d_in[0];
    const float* ln1_w  = (const float*)d_in[1];
    const float* ln1_b  = (const float*)d_in[2];
    const float* ln2_w  = (const float*)d_in[3];
    const float* ln2_b  = (const float*)d_in[4];
    const float* qkv_w  = (const float*)d_in[5];
    const float* qkv_b  = (const float*)d_in[6];
    const float* proj_w = (const float*)d_in[7];
    const float* proj_b = (const float*)d_in[8];
    const float* fc1_w  = (const float*)d_in[9];
    const float* fc1_b  = (const float*)d_in[10];
    const float* fc2_w  = (const float*)d_in[11];
    const float* fc2_b  = (const float*)d_in[12];
    float* out = (float*)d_out;

    void* p;
    cudaGetSymbolAddress(&p, g_xn);    __half* xn   = (__half*)p;
    cudaGetSymbolAddress(&p, g_qkv);   __half* qkv  = (__half*)p;
    cudaGetSymbolAddress(&p, g_att);   __half* att  = (__half*)p;
    cudaGetSymbolAddress(&p, g_x1);    float*  x1   = (float*)p;
    cudaGetSymbolAddress(&p, g_h);     __half* h    = (__half*)p;
    cudaGetSymbolAddress(&p, g_wqkv);  __half* wq   = (__half*)p;
    cudaGetSymbolAddress(&p, g_wproj); __half* wp   = (__half*)p;
    cudaGetSymbolAddress(&p, g_wfc1);  __half* w1   = (__half*)p;
    cudaGetSymbolAddress(&p, g_wfc2);  __half* w2   = (__half*)p;

    cudaFuncSetAttribute(attn_mma, cudaFuncAttributeMaxDynamicSharedMemorySize,
                         ATTN_SMEM);
    cudaFuncSetAttribute(gemm_fp16<0>, cudaFuncAttributeMaxDynamicSharedMemorySize,
                         GEMM_SMEM);
    cudaFuncSetAttribute(gemm_fp16<1>, cudaFuncAttributeMaxDynamicSharedMemorySize,
                         GEMM_SMEM);
    cudaFuncSetAttribute(gemm_fp16<2>, cudaFuncAttributeMaxDynamicSharedMemorySize,
                         GEMM_SMEM);

    // Weights -> fp16 (RN)
    cvt_h_kernel<<<EMBED * QKV_C / 4 / 256, 256>>>(qkv_w, wq, EMBED * QKV_C / 4);
    cvt_h_kernel<<<EMBED * EMBED / 4 / 256, 256>>>(proj_w, wp, EMBED * EMBED / 4);
    cvt_h_kernel<<<EMBED * HIDDEN / 4 / 256, 256>>>(fc1_w, w1, EMBED * HIDDEN / 4);
    cvt_h_kernel<<<HIDDEN * EMBED / 4 / 256, 256>>>(fc2_w, w2, HIDDEN * EMBED / 4);

    // x1 = x + proj(attn(ln1(x)))
    ln_kernel<<<ROWS, 256>>>(x, ln1_w, ln1_b, xn);
    gemm_fp16<0><<<dim3(QKV_C / BN, ROWS / BM), 128, GEMM_SMEM>>>(
        xn, wq, qkv_b, nullptr, nullptr, qkv, EMBED, QKV_C);
    attn_mma<<<dim3(SEQ / QROWS, BATCH * HEADS), 256, ATTN_SMEM>>>(qkv, att);
    gemm_fp16<2><<<dim3(EMBED / BN, ROWS / BM), 128, GEMM_SMEM>>>(
        att, wp, proj_b, x, x1, nullptr, EMBED, EMBED);

    // out = x1 + fc2(gelu(fc1(ln2(x1))))
    ln_kernel<<<ROWS, 256>>>(x1, ln2_w, ln2_b, xn);
    gemm_fp16<1><<<dim3(HIDDEN / BN, ROWS / BM), 128, GEMM_SMEM>>>(
        xn, w1, fc1_b, nullptr, nullptr, h, EMBED, HIDDEN);
    gemm_fp16<2><<<dim3(EMBED / BN, ROWS / BM), 128, GEMM_SMEM>>>(
        h, w2, fc2_b, x1, out, nullptr, HIDDEN, EMBED);
}

// round 15
// speedup vs baseline: 7.7621x; 1.0276x over previous
#include <cuda_runtime.h>
#include <cuda_fp16.h>
#include <math.h>
#include <stdint.h>

#define EMBED 1024
#define HEADS 16
#define HEAD_DIM 64
#define HIDDEN 4096
#define BATCH 2
#define SEQ 2048
#define ROWS (BATCH * SEQ)
#define QKV_C (3 * EMBED)

// ---- GEMM tiling (fp16 operands) ----
#define BM 128
#define BN 128
#define BKH 64        // K halves per chunk
#define STAGES 3
#define APH 72        // A pitch (halves): 144B rows, conflict-free quads
#define BPH 136       // B pitch (halves): 272B rows, conflict-free quads
#define ASTGH (BM * APH)          // 9216 halves
#define BSTGH (BKH * BPH)         // 8704 halves
#define STGH (ASTGH + BSTGH)      // 17920 halves / stage
#define GEMM_SMEM (STGH * STAGES * 2)  // 107520 B

// ---- Attention tiling (fp16) ----
#define QROWS 128
#define QPH 72        // pitch for Q/K/V/P (halves)
#define KVSTGH (128 * QPH)        // K tile + V tile halves per stage
#define ATTN_SMEM ((QROWS * QPH + 2 * KVSTGH) * 2)  // 55296 B

// Scratch (no cudaMalloc allowed)
__device__ __half g_xn[(size_t)ROWS * EMBED];
__device__ __half g_qkv[(size_t)ROWS * QKV_C];
__device__ __half g_att[(size_t)ROWS * EMBED];
__device__ float  g_x1[(size_t)ROWS * EMBED];
__device__ __half g_h[(size_t)ROWS * HIDDEN];
__device__ __half g_wqkv[(size_t)EMBED * QKV_C];
__device__ __half g_wproj[(size_t)EMBED * EMBED];
__device__ __half g_wfc1[(size_t)EMBED * HIDDEN];
__device__ __half g_wfc2[(size_t)HIDDEN * EMBED];

// ---------------------------------------------------------------------------
__device__ __forceinline__ float gelu_exact(float x) {
    return 0.5f * x * (1.0f + erff(x * 0.70710678118654752f));
}

__device__ __forceinline__ void mma_fp16(float c[4], const uint32_t a[4],
                                         const uint32_t b[2]) {
    asm volatile(
        "mma.sync.aligned.m16n8k16.row.col.f32.f16.f16.f32 "
        "{%0,%1,%2,%3},{%4,%5,%6,%7},{%8,%9},{%0,%1,%2,%3};\n"
        : "+f"(c[0]), "+f"(c[1]), "+f"(c[2]), "+f"(c[3])
        : "r"(a[0]), "r"(a[1]), "r"(a[2]), "r"(a[3]), "r"(b[0]), "r"(b[1]));
}

__device__ __forceinline__ void cp16(uint32_t saddr, const void* gptr) {
    asm volatile("cp.async.cg.shared.global [%0], [%1], 16;\n" ::"r"(saddr),
                 "l"(gptr));
}

__device__ __forceinline__ void ldsm4(uint32_t r[4], uint32_t saddr) {
    asm volatile(
        "ldmatrix.sync.aligned.m8n8.x4.shared.b16 {%0,%1,%2,%3}, [%4];\n"
        : "=r"(r[0]), "=r"(r[1]), "=r"(r[2]), "=r"(r[3])
        : "r"(saddr));
}

__device__ __forceinline__ void ldsm4t(uint32_t r[4], uint32_t saddr) {
    asm volatile(
        "ldmatrix.sync.aligned.m8n8.x4.trans.shared.b16 {%0,%1,%2,%3}, [%4];\n"
        : "=r"(r[0]), "=r"(r[1]), "=r"(r[2]), "=r"(r[3])
        : "r"(saddr));
}

// ---------------------------------------------------------------------------
// Weight fp32 -> fp16 conversion (once per launch)
// ---------------------------------------------------------------------------
__global__ __launch_bounds__(256) void cvt_h_kernel(const float* __restrict__ in,
                                                    __half* __restrict__ out,
                                                    int n4) {
    int i = blockIdx.x * blockDim.x + threadIdx.x;
    if (i < n4) {
        float4 v = ((const float4*)in)[i];
        __half2 h0 = __floats2half2_rn(v.x, v.y);
        __half2 h1 = __floats2half2_rn(v.z, v.w);
        uint2 u;
        u.x = *(uint32_t*)&h0;
        u.y = *(uint32_t*)&h1;
        *(uint2*)(out + 4 * (size_t)i) = u;
    }
}

// ---------------------------------------------------------------------------
// LayerNorm -> fp16 output (consumed only as GEMM A operand)
// ---------------------------------------------------------------------------
__global__ __launch_bounds__(256) void ln_kernel(const float* __restrict__ x,
                                                 const float* __restrict__ w,
                                                 const float* __restrict__ b,
                                                 __half* __restrict__ out) {
    int row = blockIdx.x;
    int t = threadIdx.x;
    const float4* xr = (const float4*)(x + (size_t)row * EMBED);
    float4 v = xr[t];
    float s = v.x + v.y + v.z + v.w;
    float q = v.x * v.x + v.y * v.y + v.z * v.z + v.w * v.w;
#pragma unroll
    for (int o = 16; o > 0; o >>= 1) {
        s += __shfl_xor_sync(0xffffffffu, s, o);
        q += __shfl_xor_sync(0xffffffffu, q, o);
    }
    __shared__ float rs[8], rq[8];
    if ((t & 31) == 0) { rs[t >> 5] = s; rq[t >> 5] = q; }
    __syncthreads();
    float ts = 0.f, tq = 0.f;
#pragma unroll
    for (int i = 0; i < 8; i++) { ts += rs[i]; tq += rq[i]; }
    float mu = ts * (1.0f / EMBED);
    float var = tq * (1.0f / EMBED) - mu * mu;
    float rstd = rsqrtf(var + 1e-5f);
    float4 wv = ((const float4*)w)[t];
    float4 bv = ((const float4*)b)[t];
    float o0 = (v.x - mu) * rstd * wv.x + bv.x;
    float o1 = (v.y - mu) * rstd * wv.y + bv.y;
    float o2 = (v.z - mu) * rstd * wv.z + bv.z;
    float o3 = (v.w - mu) * rstd * wv.w + bv.w;
    __half2 h0 = __floats2half2_rn(o0, o1);
    __half2 h1 = __floats2half2_rn(o2, o3);
    uint2 u;
    u.x = *(uint32_t*)&h0;
    u.y = *(uint32_t*)&h1;
    *(uint2*)(out + (size_t)row * EMBED + t * 4) = u;
}

// ---------------------------------------------------------------------------
// fp16 GEMM: 256 threads, 8 warps of 32x64, BKH=64, 3-stage cp.async,
// 2 CTAs/SM (16 warps/SM).
// EPI: 0 = bias -> half, 1 = bias + GELU -> half, 2 = bias + residual -> fp32
// ---------------------------------------------------------------------------
template <int EPI>
__global__ __launch_bounds__(256, 2) void gemm_fp16(
    const __half* __restrict__ A, const __half* __restrict__ W,
    const float* __restrict__ bias, const float* __restrict__ res,
    float* __restrict__ C, __half* __restrict__ Ch, int K, int Nc) {
    extern __shared__ __half smh[];
    const uint32_t sb = (uint32_t)__cvta_generic_to_shared(smh);
    const int tid = threadIdx.x;
    const int warp = tid >> 5, lane = tid & 31;
    const int g = lane >> 2, t = lane & 3;
    const int wm = (warp >> 1) * 32, wn = (warp & 1) * 64;
    const int brow = blockIdx.y, bcol = blockIdx.x;

    const __half* Aptr = A + (size_t)(brow * BM) * K;
    const __half* Wptr = W + (size_t)bcol * BN;

    // loaders (256 threads): A 128 rows x 8 chunks; B 64 rows x 16 chunks
    const int ar0 = tid >> 3;          // 0..31, +32*i
    const int ac = tid & 7;
    const int br0 = tid >> 4;          // 0..15, +16*i
    const int bc = tid & 15;

    // ldmatrix lane offsets (bytes)
    const uint32_t a_off =
        (uint32_t)(((lane & 7) + 8 * ((lane >> 3) & 1)) * APH * 2 +
                   (lane >> 4) * 16);
    const uint32_t b_off =
        (uint32_t)(((lane & 7) + 8 * ((lane >> 3) & 1)) * BPH * 2 +
                   (lane >> 4) * 16);

    float acc[2][8][4];
#pragma unroll
    for (int i = 0; i < 2; i++)
#pragma unroll
        for (int j = 0; j < 8; j++)
#pragma unroll
            for (int c = 0; c < 4; c++) acc[i][j][c] = 0.f;

    const int nch = K / BKH;

    auto issue = [&](int kt) {
        const int s = kt % STAGES;
        const uint32_t Asm = sb + (uint32_t)(s * STGH) * 2u;
        const uint32_t Bsm = Asm + ASTGH * 2u;
#pragma unroll
        for (int i = 0; i < 4; i++) {
            const int r = ar0 + 32 * i;
            cp16(Asm + (uint32_t)(r * APH + ac * 8) * 2u,
                 Aptr + (size_t)r * K + kt * BKH + ac * 8);
        }
#pragma unroll
        for (int i = 0; i < 4; i++) {
            const int r = br0 + 16 * i;
            cp16(Bsm + (uint32_t)(r * BPH + bc * 8) * 2u,
                 Wptr + (size_t)(kt * BKH + r) * Nc + bc * 8);
        }
    };

    issue(0);
    asm volatile("cp.async.commit_group;" ::: "memory");
    issue(1);
    asm volatile("cp.async.commit_group;" ::: "memory");

    for (int kt = 0; kt < nch; kt++) {
        asm volatile("cp.async.wait_group 1;" ::: "memory");
        __syncthreads();

        const int s = kt % STAGES;
        const uint32_t Astage = sb + (uint32_t)(s * STGH) * 2u;
        const uint32_t Bstage = Astage + ASTGH * 2u;

#pragma unroll
        for (int ks = 0; ks < 4; ks++) {
            uint32_t bfr[8][2];
#pragma unroll
            for (int jj = 0; jj < 4; jj++) {
                uint32_t r4[4];
                ldsm4t(r4, Bstage + (uint32_t)(ks * 16 * BPH * 2) +
                               (uint32_t)((wn + jj * 16) * 2) + b_off);
                bfr[2 * jj][0] = r4[0];
                bfr[2 * jj][1] = r4[1];
                bfr[2 * jj + 1][0] = r4[2];
                bfr[2 * jj + 1][1] = r4[3];
            }
#pragma unroll
            for (int i = 0; i < 2; i++) {
                uint32_t afr[4];
                ldsm4(afr, Astage + (uint32_t)((wm + i * 16) * APH * 2) +
                               (uint32_t)(ks * 32) + a_off);
#pragma unroll
                for (int j = 0; j < 8; j++) mma_fp16(acc[i][j], afr, bfr[j]);
            }
        }

        if (kt + 2 < nch) issue(kt + 2);
        asm volatile("cp.async.commit_group;" ::: "memory");
    }

    // Epilogue
    const int colb = bcol * BN + wn;
#pragma unroll
    for (int i = 0; i < 2; i++) {
        const size_t r0 = (size_t)(brow * BM + wm + i * 16 + g);
        const size_t r1 = r0 + 8;
#pragma unroll
        for (int j = 0; j < 8; j++) {
            const int c0 = colb + j * 8 + 2 * t;
            float2 bv = *(const float2*)(bias + c0);
            float o0x = acc[i][j][0] + bv.x, o0y = acc[i][j][1] + bv.y;
            float o1x = acc[i][j][2] + bv.x, o1y = acc[i][j][3] + bv.y;
            if (EPI == 0) {
                *(__half2*)(Ch + r0 * Nc + c0) = __floats2half2_rn(o0x, o0y);
                *(__half2*)(Ch + r1 * Nc + c0) = __floats2half2_rn(o1x, o1y);
            } else if (EPI == 1) {
                *(__half2*)(Ch + r0 * Nc + c0) =
                    __floats2half2_rn(gelu_exact(o0x), gelu_exact(o0y));
                *(__half2*)(Ch + r1 * Nc + c0) =
                    __floats2half2_rn(gelu_exact(o1x), gelu_exact(o1y));
            } else {
                float2 r0v = *(const float2*)(res + r0 * Nc + c0);
                float2 r1v = *(const float2*)(res + r1 * Nc + c0);
                *(float2*)(C + r0 * Nc + c0) =
                    make_float2(o0x + r0v.x, o0y + r0v.y);
                *(float2*)(C + r1 * Nc + c0) =
                    make_float2(o1x + r1v.x, o1y + r1v.y);
            }
        }
    }
}

// ---------------------------------------------------------------------------
// fp16 flash attention: 8 warps, 128 q-rows/CTA, 64-key tiles, cp.async
// double-buffered K/V, ldmatrix fragments everywhere. Output fp16.
// ---------------------------------------------------------------------------
__global__ __launch_bounds__(256) void attn_mma(const __half* __restrict__ qkv,
                                                __half* __restrict__ out) {
    extern __shared__ __half sma[];
    __half* Qs = sma;  // [128][QPH]; warp's 16-row block doubles as P
    const uint32_t sb = (uint32_t)__cvta_generic_to_shared(sma);
    const uint32_t kvb = sb + (uint32_t)(QROWS * QPH * 2);

    const int bh = blockIdx.y;
    const int b = bh >> 4, h = bh & 15;
    const int qblk = blockIdx.x;
    const int tid = threadIdx.x;
    const int w = tid >> 5, lane = tid & 31;
    const int g = lane >> 2, t = lane & 3;
    const int wm = w * 16;

    const __half* qbase =
        qkv + (size_t)(b * SEQ + qblk * QROWS) * QKV_C + h * HEAD_DIM;
    const __half* kbase = qkv + (size_t)(b * SEQ) * QKV_C + EMBED + h * HEAD_DIM;
    const __half* vbase =
        qkv + (size_t)(b * SEQ) * QKV_C + 2 * EMBED + h * HEAD_DIM;

    // K/V tile loader: 64 rows x 8 chunks each; 256 threads, 2 passes
    auto issue_kv = [&](int tt, int s) {
        const uint32_t kd = kvb + (uint32_t)(s * KVSTGH) * 2u;
        const uint32_t vd = kd + (uint32_t)(64 * QPH * 2);
        const __half* kp = kbase + (size_t)(tt * 64) * QKV_C;
        const __half* vp = vbase + (size_t)(tt * 64) * QKV_C;
#pragma unroll
        for (int i = 0; i < 2; i++) {
            const int idx = tid + 256 * i;
            const int r = idx >> 3, c = idx & 7;
            cp16(kd + (uint32_t)(r * QPH + c * 8) * 2u,
                 kp + (size_t)r * QKV_C + c * 8);
            cp16(vd + (uint32_t)(r * QPH + c * 8) * 2u,
                 vp + (size_t)r * QKV_C + c * 8);
        }
    };

    issue_kv(0, 0);
    asm volatile("cp.async.commit_group;" ::: "memory");
    issue_kv(1, 1);
    asm volatile("cp.async.commit_group;" ::: "memory");

    // Stage Q (pre-scaled by 1/8, exact in fp16)
    {
        const __half2 sc = __floats2half2_rn(0.125f, 0.125f);
        for (int idx = tid; idx < QROWS * 32; idx += 256) {
            int r = idx >> 5, c2 = idx & 31;
            __half2 v = *(const __half2*)(qbase + (size_t)r * QKV_C + c2 * 2);
            *(__half2*)(Qs + r * QPH + c2 * 2) = __hmul2(v, sc);
        }
    }
    __syncthreads();

    // ldmatrix lane offsets (bytes)
    const uint32_t a_off =
        (uint32_t)(((lane & 7) + 8 * ((lane >> 3) & 1)) * QPH * 2 +
                   (lane >> 4) * 16);
    const uint32_t k_off =
        (uint32_t)(((lane & 7) + 8 * (lane >> 4)) * QPH * 2 +
                   ((lane >> 3) & 1) * 16);
    const uint32_t v_off = a_off;  // same pattern (rows + dim-chunk select)
    const uint32_t pqbase = sb + (uint32_t)(wm * QPH * 2);

    // Q fragments (warp's own 16 rows)
    uint32_t qa[4][4];
#pragma unroll
    for (int kk = 0; kk < 4; kk++) ldsm4(qa[kk], pqbase + kk * 32 + a_off);

    __half* Pw = Qs + wm * QPH;

    float m0 = -INFINITY, m1 = -INFINITY, l0 = 0.f, l1 = 0.f;
    float o[8][4];
#pragma unroll
    for (int j = 0; j < 8; j++)
#pragma unroll
        for (int c = 0; c < 4; c++) o[j][c] = 0.f;

    const int ntiles = SEQ / 64;
    for (int it = 0; it < ntiles; it++) {
        asm volatile("cp.async.wait_group 1;" ::: "memory");
        __syncthreads();

        const int s = it & 1;
        const uint32_t Kbase = kvb + (uint32_t)(s * KVSTGH) * 2u;
        const uint32_t Vbase = Kbase + (uint32_t)(64 * QPH * 2);

        // S = (Q/8) @ K^T
        float sacc[8][4];
#pragma unroll
        for (int j = 0; j < 8; j++)
#pragma unroll
            for (int c = 0; c < 4; c++) sacc[j][c] = 0.f;
#pragma unroll
        for (int kk = 0; kk < 4; kk++) {
            uint32_t kfr[8][2];
#pragma unroll
            for (int jj = 0; jj < 4; jj++) {
                uint32_t r4[4];
                ldsm4(r4, Kbase + (uint32_t)(jj * 16 * QPH * 2) + kk * 32 + k_off);
                kfr[2 * jj][0] = r4[0];
                kfr[2 * jj][1] = r4[1];
                kfr[2 * jj + 1][0] = r4[2];
                kfr[2 * jj + 1][1] = r4[3];
            }
#pragma unroll
            for (int j = 0; j < 8; j++) mma_fp16(sacc[j], qa[kk], kfr[j]);
        }

        // Online softmax (rows g, g+8; reduce over quad lanes)
        float mx0 = -INFINITY, mx1 = -INFINITY;
#pragma unroll
        for (int j = 0; j < 8; j++) {
            mx0 = fmaxf(mx0, fmaxf(sacc[j][0], sacc[j][1]));
            mx1 = fmaxf(mx1, fmaxf(sacc[j][2], sacc[j][3]));
        }
#pragma unroll
        for (int off = 1; off < 4; off <<= 1) {
            mx0 = fmaxf(mx0, __shfl_xor_sync(0xffffffffu, mx0, off));
            mx1 = fmaxf(mx1, __shfl_xor_sync(0xffffffffu, mx1, off));
        }
        float mn0 = fmaxf(m0, mx0), mn1 = fmaxf(m1, mx1);
        float a0 = __expf(m0 - mn0), a1 = __expf(m1 - mn1);
        float s0 = 0.f, s1 = 0.f;
#pragma unroll
        for (int j = 0; j < 8; j++) {
            float p0 = __expf(sacc[j][0] - mn0);
            float p1 = __expf(sacc[j][1] - mn0);
            float p2 = __expf(sacc[j][2] - mn1);
            float p3 = __expf(sacc[j][3] - mn1);
            s0 += p0 + p1;
            s1 += p2 + p3;
            *(__half2*)(Pw + g * QPH + j * 8 + 2 * t) = __floats2half2_rn(p0, p1);
            *(__half2*)(Pw + (g + 8) * QPH + j * 8 + 2 * t) =
                __floats2half2_rn(p2, p3);
        }
#pragma unroll
        for (int off = 1; off < 4; off <<= 1) {
            s0 += __shfl_xor_sync(0xffffffffu, s0, off);
            s1 += __shfl_xor_sync(0xffffffffu, s1, off);
        }
        l0 = l0 * a0 + s0;
        l1 = l1 * a1 + s1;
        m0 = mn0;
        m1 = mn1;
#pragma unroll
        for (int j = 0; j < 8; j++) {
            o[j][0] *= a0; o[j][1] *= a0; o[j][2] *= a1; o[j][3] *= a1;
        }
        __syncwarp();

        // O += P @ V
#pragma unroll
        for (int kk = 0; kk < 4; kk++) {
            uint32_t pa[4];
            ldsm4(pa, pqbase + kk * 32 + a_off);
            uint32_t vfr[8][2];
#pragma unroll
            for (int jj = 0; jj < 4; jj++) {
                uint32_t r4[4];
                ldsm4t(r4,
                       Vbase + (uint32_t)(kk * 16 * QPH * 2) + jj * 32 + v_off);
                vfr[2 * jj][0] = r4[0];
                vfr[2 * jj][1] = r4[1];
                vfr[2 * jj + 1][0] = r4[2];
                vfr[2 * jj + 1][1] = r4[3];
            }
#pragma unroll
            for (int j = 0; j < 8; j++) mma_fp16(o[j], pa, vfr[j]);
        }

        __syncthreads();
        if (it + 2 < ntiles) issue_kv(it + 2, s);
        asm volatile("cp.async.commit_group;" ::: "memory");
    }

    // Epilogue: normalize -> fp16 (feeds proj GEMM A)
    float inv0 = 1.f / l0, inv1 = 1.f / l1;
    const int row0 = qblk * QROWS + wm + g;
    __half* ob = out + (size_t)(b * SEQ) * EMBED + h * HEAD_DIM;
#pragma unroll
    for (int j = 0; j < 8; j++) {
        *(__half2*)(ob + (size_t)row0 * EMBED + j * 8 + 2 * t) =
            __floats2half2_rn(o[j][0] * inv0, o[j][1] * inv0);
        *(__half2*)(ob + (size_t)(row0 + 8) * EMBED + j * 8 + 2 * t) =
            __floats2half2_rn(o[j][2] * inv1, o[j][3] * inv1);
    }
}

// ---------------------------------------------------------------------------
extern "C" void kernel_launch(void* const* d_in, const int* in_sizes, int n_in,
                              void* d_out, int out_size) {
    const float* x      = (const float*)d_in[0];
    const float* ln1_w  = (const float*)d_in[1];
    const float* ln1_b  = (const float*)d_in[2];
    const float* ln2_w  = (const float*)d_in[3];
    const float* ln2_b  = (const float*)d_in[4];
    const float* qkv_w  = (const float*)d_in[5];
    const float* qkv_b  = (const float*)d_in[6];
    const float* proj_w = (const float*)d_in[7];
    const float* proj_b = (const float*)d_in[8];
    const float* fc1_w  = (const float*)d_in[9];
    const float* fc1_b  = (const float*)d_in[10];
    const float* fc2_w  = (const float*)d_in[11];
    const float* fc2_b  = (const float*)d_in[12];
    float* out = (float*)d_out;

    void* p;
    cudaGetSymbolAddress(&p, g_xn);    __half* xn   = (__half*)p;
    cudaGetSymbolAddress(&p, g_qkv);   __half* qkv  = (__half*)p;
    cudaGetSymbolAddress(&p, g_att);   __half* att  = (__half*)p;
    cudaGetSymbolAddress(&p, g_x1);    float*  x1   = (float*)p;
    cudaGetSymbolAddress(&p, g_h);     __half* h    = (__half*)p;
    cudaGetSymbolAddress(&p, g_wqkv);  __half* wq   = (__half*)p;
    cudaGetSymbolAddress(&p, g_wproj); __half* wp   = (__half*)p;
    cudaGetSymbolAddress(&p, g_wfc1);  __half* w1   = (__half*)p;
    cudaGetSymbolAddress(&p, g_wfc2);  __half* w2   = (__half*)p;

    cudaFuncSetAttribute(attn_mma, cudaFuncAttributeMaxDynamicSharedMemorySize,
                         ATTN_SMEM);
    cudaFuncSetAttribute(gemm_fp16<0>, cudaFuncAttributeMaxDynamicSharedMemorySize,
                         GEMM_SMEM);
    cudaFuncSetAttribute(gemm_fp16<1>, cudaFuncAttributeMaxDynamicSharedMemorySize,
                         GEMM_SMEM);
    cudaFuncSetAttribute(gemm_fp16<2>, cudaFuncAttributeMaxDynamicSharedMemorySize,
                         GEMM_SMEM);

    // Weights -> fp16 (RN)
    cvt_h_kernel<<<EMBED * QKV_C / 4 / 256, 256>>>(qkv_w, wq, EMBED * QKV_C / 4);
    cvt_h_kernel<<<EMBED * EMBED / 4 / 256, 256>>>(proj_w, wp, EMBED * EMBED / 4);
    cvt_h_kernel<<<EMBED * HIDDEN / 4 / 256, 256>>>(fc1_w, w1, EMBED * HIDDEN / 4);
    cvt_h_kernel<<<HIDDEN * EMBED / 4 / 256, 256>>>(fc2_w, w2, HIDDEN * EMBED / 4);

    // x1 = x + proj(attn(ln1(x)))
    ln_kernel<<<ROWS, 256>>>(x, ln1_w, ln1_b, xn);
    gemm_fp16<0><<<dim3(QKV_C / BN, ROWS / BM), 256, GEMM_SMEM>>>(
        xn, wq, qkv_b, nullptr, nullptr, qkv, EMBED, QKV_C);
    attn_mma<<<dim3(SEQ / QROWS, BATCH * HEADS), 256, ATTN_SMEM>>>(qkv, att);
    gemm_fp16<2><<<dim3(EMBED / BN, ROWS / BM), 256, GEMM_SMEM>>>(
        att, wp, proj_b, x, x1, nullptr, EMBED, EMBED);

    // out = x1 + fc2(gelu(fc1(ln2(x1))))
    ln_kernel<<<ROWS, 256>>>(x1, ln2_w, ln2_b, xn);
    gemm_fp16<1><<<dim3(HIDDEN / BN, ROWS / BM), 256, GEMM_SMEM>>>(
        xn, w1, fc1_b, nullptr, nullptr, h, EMBED, HIDDEN);
    gemm_fp16<2><<<dim3(EMBED / BN, ROWS / BM), 256, GEMM_SMEM>>>(
        h, w2, fc2_b, x1, out, nullptr, HIDDEN, EMBED);
}